// round 1
// baseline (speedup 1.0000x reference)
#include <cuda_runtime.h>
#include <cuda_bf16.h>
#include <math.h>

// Problem constants
#define NMAX 50000
#define EMAX 300000
#define INDIM 128
#define HID 64
#define HEADS 4
#define QKVDIM 256      // HEADS*HID
#define COLS_ALL 832    // 3*256 + 64 (Wq|Wk|Wv|Wskip)
#define OUTD 64

// ---------------- scratch (static device globals; no runtime alloc) ----------------
__device__ float g_Wall[INDIM * COLS_ALL];
__device__ float g_ball[COLS_ALL];
__device__ float g_q[(size_t)NMAX * QKVDIM];
__device__ float g_k[(size_t)NMAX * QKVDIM];
__device__ float g_v[(size_t)NMAX * QKVDIM];
__device__ float g_skip[(size_t)NMAX * HID];
__device__ float g_alpha[(size_t)EMAX * HEADS];
__device__ float g_ex[(size_t)EMAX * HEADS];
__device__ int   g_menc[(size_t)NMAX * HEADS];
__device__ float g_denom[(size_t)NMAX * HEADS];
__device__ float g_agg[(size_t)NMAX * QKVDIM];
__device__ float g_Wms[HID * OUTD];

// ---------------- helpers ----------------
__device__ __forceinline__ int enc_f(float f) {
    int i = __float_as_int(f);
    return (i >= 0) ? i : (i ^ 0x7FFFFFFF);
}
__device__ __forceinline__ float dec_f(int i) {
    return (i >= 0) ? __int_as_float(i) : __int_as_float(i ^ 0x7FFFFFFF);
}
__device__ __forceinline__ void red_add_v4(float* p, float x, float y, float z, float w) {
    asm volatile("red.global.add.v4.f32 [%0], {%1,%2,%3,%4};"
                 :: "l"(p), "f"(x), "f"(y), "f"(z), "f"(w) : "memory");
}

// ---------------- kernel: pack weights + biases ----------------
__global__ void prep_kernel(const float* __restrict__ Wq, const float* __restrict__ bq,
                            const float* __restrict__ Wk, const float* __restrict__ bk,
                            const float* __restrict__ Wv, const float* __restrict__ bv,
                            const float* __restrict__ Ws, const float* __restrict__ bs) {
    int i = blockIdx.x * blockDim.x + threadIdx.x;
    if (i < COLS_ALL) {
        float b = (i < 256) ? bq[i] : (i < 512) ? bk[i - 256] : (i < 768) ? bv[i - 512] : bs[i - 768];
        g_ball[i] = b;
    }
    if (i < INDIM * COLS_ALL) {
        int r = i / COLS_ALL, c = i % COLS_ALL;
        float w = (c < 256) ? Wq[r * 256 + c]
                : (c < 512) ? Wk[r * 256 + c - 256]
                : (c < 768) ? Wv[r * 256 + c - 512]
                :             Ws[r * 64  + c - 768];
        g_Wall[i] = w;
    }
}

// ---------------- kernel: spectral norm power iteration (exact replica) ----------------
__global__ void sigma_kernel(const float* __restrict__ Wmlp) {
    __shared__ float Wsh[64][65];
    __shared__ float u[64], vv[64], upre[64], red[64];
    int t = threadIdx.x;  // 64 threads
    for (int i = 0; i < 64; ++i) Wsh[i][t] = Wmlp[i * 64 + t];
    u[t] = 0.125f;  // ones(64)/||ones|| exactly
    __syncthreads();
    for (int it = 0; it < 20; ++it) {
        // v = W^T u
        float s = 0.f;
        for (int i = 0; i < 64; ++i) s += Wsh[i][t] * u[i];
        red[t] = s * s; __syncthreads();
        for (int off = 32; off > 0; off >>= 1) { if (t < off) red[t] += red[t + off]; __syncthreads(); }
        float nv = sqrtf(red[0]);
        vv[t] = s / (nv + 1e-12f);
        __syncthreads();
        // u = W v
        float s2 = 0.f;
        for (int j = 0; j < 64; ++j) s2 += Wsh[t][j] * vv[j];
        upre[t] = s2;
        red[t] = s2 * s2; __syncthreads();
        for (int off = 32; off > 0; off >>= 1) { if (t < off) red[t] += red[t + off]; __syncthreads(); }
        float nu = sqrtf(red[0]);
        u[t] = s2 / (nu + 1e-12f);
        __syncthreads();
    }
    red[t] = u[t] * upre[t]; __syncthreads();
    for (int off = 32; off > 0; off >>= 1) { if (t < off) red[t] += red[t + off]; __syncthreads(); }
    float sigma = red[0];
    for (int j = 0; j < 64; ++j) g_Wms[t * 64 + j] = Wsh[t][j] / sigma;
}

// ---------------- kernel: init scratch ----------------
__global__ void init_kernel(int n) {
    int i = blockIdx.x * blockDim.x + threadIdx.x;
    if (i < n * 64) reinterpret_cast<float4*>(g_agg)[i] = make_float4(0.f, 0.f, 0.f, 0.f);
    if (i < n * HEADS) {
        g_denom[i] = 0.f;
        g_menc[i] = 0x807FFFFF;  // enc(-inf)
    }
}

// ---------------- kernel: fused projection GEMM [N,128] x [128,832] ----------------
__global__ void gemm_kernel(const float* __restrict__ x, int nrows) {
    __shared__ float xs[64][68];
    __shared__ float ws[64][72];
    int row0 = blockIdx.x * 64;
    int col0 = blockIdx.y * 64;
    int tid = threadIdx.x;
    int tx = tid & 15, ty = tid >> 4;
    float acc[4][4] = {};

    for (int s = 0; s < 2; ++s) {
#pragma unroll
        for (int i = 0; i < 4; ++i) {
            int idx = tid + i * 256;
            int r = idx >> 4, c4 = idx & 15;
            float4 val = make_float4(0.f, 0.f, 0.f, 0.f);
            int gr = row0 + r;
            if (gr < nrows) val = *reinterpret_cast<const float4*>(x + (size_t)gr * INDIM + s * 64 + c4 * 4);
            *reinterpret_cast<float4*>(&xs[r][c4 * 4]) = val;
        }
#pragma unroll
        for (int i = 0; i < 4; ++i) {
            int idx = tid + i * 256;
            int r = idx >> 4, c4 = idx & 15;
            float4 w = *reinterpret_cast<const float4*>(&g_Wall[(size_t)(s * 64 + r) * COLS_ALL + col0 + c4 * 4]);
            *reinterpret_cast<float4*>(&ws[r][c4 * 4]) = w;
        }
        __syncthreads();
#pragma unroll 8
        for (int k = 0; k < 64; ++k) {
            float a0 = xs[ty * 4 + 0][k];
            float a1 = xs[ty * 4 + 1][k];
            float a2 = xs[ty * 4 + 2][k];
            float a3 = xs[ty * 4 + 3][k];
            float4 b = *reinterpret_cast<const float4*>(&ws[k][tx * 4]);
            acc[0][0] += a0 * b.x; acc[0][1] += a0 * b.y; acc[0][2] += a0 * b.z; acc[0][3] += a0 * b.w;
            acc[1][0] += a1 * b.x; acc[1][1] += a1 * b.y; acc[1][2] += a1 * b.z; acc[1][3] += a1 * b.w;
            acc[2][0] += a2 * b.x; acc[2][1] += a2 * b.y; acc[2][2] += a2 * b.z; acc[2][3] += a2 * b.w;
            acc[3][0] += a3 * b.x; acc[3][1] += a3 * b.y; acc[3][2] += a3 * b.z; acc[3][3] += a3 * b.w;
        }
        __syncthreads();
    }

#pragma unroll
    for (int i = 0; i < 4; ++i) {
        int gr = row0 + ty * 4 + i;
        if (gr >= nrows) continue;
#pragma unroll
        for (int j = 0; j < 4; ++j) {
            int gc = col0 + tx * 4 + j;
            float val = acc[i][j] + g_ball[gc];
            if (gc < 256)      g_q[(size_t)gr * QKVDIM + gc] = val;
            else if (gc < 512) g_k[(size_t)gr * QKVDIM + gc - 256] = val;
            else if (gc < 768) g_v[(size_t)gr * QKVDIM + gc - 512] = val;
            else               g_skip[(size_t)gr * HID + gc - 768] = val;
        }
    }
}

// ---------------- kernel: per-edge attention logits + segment max ----------------
__global__ void edge_logits_kernel(const int* __restrict__ ei, int E) {
    int gtid = blockIdx.x * blockDim.x + threadIdx.x;
    int e = gtid >> 5;
    if (e >= E) return;
    int l = gtid & 31;
    int src = ei[e], dst = ei[E + e];
    const float4* q4 = reinterpret_cast<const float4*>(g_q + (size_t)dst * QKVDIM);
    const float4* k4 = reinterpret_cast<const float4*>(g_k + (size_t)src * QKVDIM);
    float4 qa = q4[l],      ka = k4[l];
    float4 qb = q4[l + 32], kb = k4[l + 32];
    float acc1 = qa.x * ka.x + qa.y * ka.y + qa.z * ka.z + qa.w * ka.w;
    float acc2 = qb.x * kb.x + qb.y * kb.y + qb.z * kb.z + qb.w * kb.w;
#pragma unroll
    for (int m = 8; m > 0; m >>= 1) {
        acc1 += __shfl_xor_sync(0xFFFFFFFFu, acc1, m);
        acc2 += __shfl_xor_sync(0xFFFFFFFFu, acc2, m);
    }
    if ((l & 15) == 0) {
        int h = l >> 4;
        float a1 = acc1 * 0.125f;  // / sqrt(64)
        float a2 = acc2 * 0.125f;
        g_alpha[(size_t)e * 4 + h]     = a1;
        g_alpha[(size_t)e * 4 + h + 2] = a2;
        atomicMax(&g_menc[dst * 4 + h],     enc_f(a1));
        atomicMax(&g_menc[dst * 4 + h + 2], enc_f(a2));
    }
}

// ---------------- kernel: exp + segment sum ----------------
__global__ void exp_kernel(const int* __restrict__ ei, int E) {
    int i = blockIdx.x * blockDim.x + threadIdx.x;
    if (i >= E * 4) return;
    int e = i >> 2, h = i & 3;
    int dst = ei[E + e];
    float m = dec_f(g_menc[dst * 4 + h]);
    float ex = expf(g_alpha[i] - m);
    g_ex[i] = ex;
    atomicAdd(&g_denom[dst * 4 + h], ex);
}

// ---------------- kernel: weighted message scatter ----------------
__global__ void scatter_kernel(const int* __restrict__ ei, int E) {
    int gtid = blockIdx.x * blockDim.x + threadIdx.x;
    int e = gtid >> 5;
    if (e >= E) return;
    int l = gtid & 31;
    int src = ei[e], dst = ei[E + e];
    int h1 = l >> 4;
    float a1 = g_ex[(size_t)e * 4 + h1]     / (g_denom[dst * 4 + h1]     + 1e-16f);
    float a2 = g_ex[(size_t)e * 4 + h1 + 2] / (g_denom[dst * 4 + h1 + 2] + 1e-16f);
    const float4* v4 = reinterpret_cast<const float4*>(g_v + (size_t)src * QKVDIM);
    float4 va = v4[l], vb = v4[l + 32];
    float* dp = g_agg + (size_t)dst * QKVDIM + l * 4;
    red_add_v4(dp,       a1 * va.x, a1 * va.y, a1 * va.z, a1 * va.w);
    red_add_v4(dp + 128, a2 * vb.x, a2 * vb.y, a2 * vb.z, a2 * vb.w);
}

// ---------------- kernel: head mean + skip + tanh + MLP ----------------
__global__ void final_kernel(float* __restrict__ out, int n) {
    __shared__ float Wms[64][65];
    __shared__ float hs[4][64];
    int tid = threadIdx.x;
    for (int i = tid; i < 4096; i += 256) Wms[i >> 6][i & 63] = g_Wms[i];
    int node = blockIdx.x * 4 + (tid >> 6);
    int d = tid & 63;
    float hval = 0.f;
    if (node < n) {
        const float* ag = g_agg + (size_t)node * QKVDIM;
        float s = 0.25f * (ag[d] + ag[64 + d] + ag[128 + d] + ag[192 + d]) + g_skip[(size_t)node * HID + d];
        hval = tanhf(s);
    }
    hs[tid >> 6][d] = hval;
    __syncthreads();
    if (node < n) {
        int ni = tid >> 6;
        float acc = 0.f;
#pragma unroll 16
        for (int dd = 0; dd < 64; ++dd) acc += hs[ni][dd] * Wms[dd][d];
        out[(size_t)node * OUTD + d] = acc;
    }
}

// ---------------- launch ----------------
extern "C" void kernel_launch(void* const* d_in, const int* in_sizes, int n_in,
                              void* d_out, int out_size) {
    const float* x     = (const float*)d_in[0];
    const int*   ei    = (const int*)  d_in[1];
    const float* Wq    = (const float*)d_in[2];
    const float* bq    = (const float*)d_in[3];
    const float* Wk    = (const float*)d_in[4];
    const float* bk    = (const float*)d_in[5];
    const float* Wv    = (const float*)d_in[6];
    const float* bv    = (const float*)d_in[7];
    const float* Wskip = (const float*)d_in[8];
    const float* bskip = (const float*)d_in[9];
    const float* Wmlp  = (const float*)d_in[10];
    float* out = (float*)d_out;

    int N = in_sizes[0] / INDIM;
    int E = in_sizes[1] / 2;

    prep_kernel<<<(INDIM * COLS_ALL + 255) / 256, 256>>>(Wq, bq, Wk, bk, Wv, bv, Wskip, bskip);
    sigma_kernel<<<1, 64>>>(Wmlp);
    init_kernel<<<(N * 64 + 255) / 256, 256>>>(N);

    dim3 ggrid((N + 63) / 64, COLS_ALL / 64);
    gemm_kernel<<<ggrid, 256>>>(x, N);

    int eb = (E * 32 + 255) / 256;
    edge_logits_kernel<<<eb, 256>>>(ei, E);
    exp_kernel<<<(E * 4 + 255) / 256, 256>>>(ei, E);
    scatter_kernel<<<eb, 256>>>(ei, E);
    final_kernel<<<(N + 3) / 4, 256>>>(out, N);
}

// round 3
// speedup vs baseline: 1.4597x; 1.4597x over previous
#include <cuda_runtime.h>
#include <cuda_bf16.h>
#include <math.h>
#include <stdint.h>

// Problem constants
#define NMAX 50000
#define EMAX 300000
#define INDIM 128
#define HID 64
#define HEADS 4
#define QKVDIM 256      // HEADS*HID
#define COLS_ALL 832    // 3*256 + 64 (Wq|Wk|Wv|Wskip)
#define OUTD 64
#define NTILES 13       // 832 / 64

// ---------------- scratch (static device globals; no runtime alloc) ----------------
__device__ float g_ball[COLS_ALL];
__device__ __nv_bfloat16 g_Wt_hi[COLS_ALL * INDIM];  // [n][k] transposed weights, hi part
__device__ __nv_bfloat16 g_Wt_lo[COLS_ALL * INDIM];  // lo part
__device__ float g_q[(size_t)NMAX * QKVDIM];
__device__ float g_k[(size_t)NMAX * QKVDIM];
__device__ float g_v[(size_t)NMAX * QKVDIM];
__device__ float g_skip[(size_t)NMAX * HID];
__device__ float g_alpha[(size_t)EMAX * HEADS];
__device__ float g_ex[(size_t)EMAX * HEADS];
__device__ int   g_menc[(size_t)NMAX * HEADS];
__device__ float g_denom[(size_t)NMAX * HEADS];
__device__ float g_agg[(size_t)NMAX * QKVDIM];
__device__ float g_Wms[HID * OUTD];

// ---------------- helpers ----------------
__device__ __forceinline__ int enc_f(float f) {
    int i = __float_as_int(f);
    return (i >= 0) ? i : (i ^ 0x7FFFFFFF);
}
__device__ __forceinline__ float dec_f(int i) {
    return (i >= 0) ? __int_as_float(i) : __int_as_float(i ^ 0x7FFFFFFF);
}
__device__ __forceinline__ void red_add_v4(float* p, float x, float y, float z, float w) {
    asm volatile("red.global.add.v4.f32 [%0], {%1,%2,%3,%4};"
                 :: "l"(p), "f"(x), "f"(y), "f"(z), "f"(w) : "memory");
}
__device__ __forceinline__ uint32_t smem_u32(const void* p) {
    uint32_t a;
    asm("{ .reg .u64 t; cvta.to.shared.u64 t, %1; cvt.u32.u64 %0, t; }" : "=r"(a) : "l"(p));
    return a;
}

#define LDMX4(r0, r1, r2, r3, addr) \
    asm volatile("ldmatrix.sync.aligned.m8n8.x4.shared.b16 {%0,%1,%2,%3}, [%4];" \
                 : "=r"(r0), "=r"(r1), "=r"(r2), "=r"(r3) : "r"(addr))

#define MMA16816(d, a, b0, b1) \
    asm volatile("mma.sync.aligned.m16n8k16.row.col.f32.bf16.bf16.f32 " \
                 "{%0,%1,%2,%3},{%4,%5,%6,%7},{%8,%9},{%0,%1,%2,%3};" \
                 : "+f"((d)[0]), "+f"((d)[1]), "+f"((d)[2]), "+f"((d)[3]) \
                 : "r"((a)[0]), "r"((a)[1]), "r"((a)[2]), "r"((a)[3]), "r"(b0), "r"(b1))

// ---------------- kernel: pack weights (transposed hi/lo bf16) + biases ----------------
__global__ void prep_kernel(const float* __restrict__ Wq, const float* __restrict__ bq,
                            const float* __restrict__ Wk, const float* __restrict__ bk,
                            const float* __restrict__ Wv, const float* __restrict__ bv,
                            const float* __restrict__ Ws, const float* __restrict__ bs) {
    int i = blockIdx.x * blockDim.x + threadIdx.x;
    if (i < COLS_ALL) {
        float b = (i < 256) ? bq[i] : (i < 512) ? bk[i - 256] : (i < 768) ? bv[i - 512] : bs[i - 768];
        g_ball[i] = b;
    }
    if (i < COLS_ALL * INDIM) {
        int n = i / INDIM, k = i % INDIM;
        float w = (n < 256) ? Wq[k * 256 + n]
                : (n < 512) ? Wk[k * 256 + (n - 256)]
                : (n < 768) ? Wv[k * 256 + (n - 512)]
                :             Ws[k * 64  + (n - 768)];
        __nv_bfloat16 hi = __float2bfloat16(w);
        __nv_bfloat16 lo = __float2bfloat16(w - __bfloat162float(hi));
        g_Wt_hi[i] = hi;
        g_Wt_lo[i] = lo;
    }
}

// ---------------- kernel: spectral norm power iteration (exact replica) ----------------
__global__ void sigma_kernel(const float* __restrict__ Wmlp) {
    __shared__ float Wsh[64][65];
    __shared__ float u[64], vv[64], upre[64], red[64];
    int t = threadIdx.x;  // 64 threads
    for (int i = 0; i < 64; ++i) Wsh[i][t] = Wmlp[i * 64 + t];
    u[t] = 0.125f;
    __syncthreads();
    for (int it = 0; it < 20; ++it) {
        float s = 0.f;
        for (int i = 0; i < 64; ++i) s += Wsh[i][t] * u[i];
        red[t] = s * s; __syncthreads();
        for (int off = 32; off > 0; off >>= 1) { if (t < off) red[t] += red[t + off]; __syncthreads(); }
        float nv = sqrtf(red[0]);
        vv[t] = s / (nv + 1e-12f);
        __syncthreads();
        float s2 = 0.f;
        for (int j = 0; j < 64; ++j) s2 += Wsh[t][j] * vv[j];
        upre[t] = s2;
        red[t] = s2 * s2; __syncthreads();
        for (int off = 32; off > 0; off >>= 1) { if (t < off) red[t] += red[t + off]; __syncthreads(); }
        float nu = sqrtf(red[0]);
        u[t] = s2 / (nu + 1e-12f);
        __syncthreads();
    }
    red[t] = u[t] * upre[t]; __syncthreads();
    for (int off = 32; off > 0; off >>= 1) { if (t < off) red[t] += red[t + off]; __syncthreads(); }
    float sigma = red[0];
    for (int j = 0; j < 64; ++j) g_Wms[t * 64 + j] = Wsh[t][j] / sigma;
}

// ---------------- kernel: init scratch ----------------
__global__ void init_kernel(int n) {
    int i = blockIdx.x * blockDim.x + threadIdx.x;
    if (i < n * 64) reinterpret_cast<float4*>(g_agg)[i] = make_float4(0.f, 0.f, 0.f, 0.f);
    if (i < n * HEADS) {
        g_denom[i] = 0.f;
        g_menc[i] = 0x807FFFFF;  // enc(-inf)
    }
}

// ---------------- bf16 mma.sync projection GEMM: [N,128] x [128,832] ----------------
// hi/lo bf16 split: acc += Ahi*Bhi + Ahi*Blo + Alo*Bhi (fp32 accumulate).
// CTA: 128 rows, 8 warps (4x2), warp tile 32x32, loop over 13 N-tiles of 64.
// SMEM: A resident (128x128 hi+lo), B streamed per tile (64x128 hi+lo). LDA=136 bf16 pad.
#define LDA_E 136
#define LDA_B 272
#define SM_A_HI 0
#define SM_A_LO 34816
#define SM_B_HI 69632
#define SM_B_LO 87040
#define GEMM_SMEM_BYTES 104448

__global__ void __launch_bounds__(256) gemm_mma_kernel(const float* __restrict__ x, int nrows) {
    extern __shared__ __align__(16) char sm[];
    const uint32_t s_base = smem_u32(sm);

    int tid = threadIdx.x;
    int lane = tid & 31;
    int wid = tid >> 5;
    int wm = wid & 3;        // warp row: 4 warps over M
    int wn = wid >> 2;       // warp col: 2 warps over N
    int row0 = blockIdx.x * 128;

    // ---- A fill: 128x128 fp32 -> bf16 hi/lo into padded smem ----
    {
#pragma unroll
        for (int p = 0; p < 16; ++p) {
            int idx = tid + p * 256;          // 0..4095
            int row = idx >> 5;               // 0..127
            int c4 = idx & 31;                // float4 index within row
            int gr = row0 + row;
            float4 v = make_float4(0.f, 0.f, 0.f, 0.f);
            if (gr < nrows) v = *reinterpret_cast<const float4*>(x + (size_t)gr * INDIM + c4 * 4);
            __nv_bfloat16 h0 = __float2bfloat16(v.x), h1 = __float2bfloat16(v.y);
            __nv_bfloat16 h2 = __float2bfloat16(v.z), h3 = __float2bfloat16(v.w);
            __nv_bfloat16 l0 = __float2bfloat16(v.x - __bfloat162float(h0));
            __nv_bfloat16 l1 = __float2bfloat16(v.y - __bfloat162float(h1));
            __nv_bfloat16 l2 = __float2bfloat16(v.z - __bfloat162float(h2));
            __nv_bfloat16 l3 = __float2bfloat16(v.w - __bfloat162float(h3));
            uint32_t hp0 = ((uint32_t)*(unsigned short*)&h1 << 16) | *(unsigned short*)&h0;
            uint32_t hp1 = ((uint32_t)*(unsigned short*)&h3 << 16) | *(unsigned short*)&h2;
            uint32_t lp0 = ((uint32_t)*(unsigned short*)&l1 << 16) | *(unsigned short*)&l0;
            uint32_t lp1 = ((uint32_t)*(unsigned short*)&l3 << 16) | *(unsigned short*)&l2;
            uint32_t off = (uint32_t)row * LDA_B + (uint32_t)c4 * 8;
            *reinterpret_cast<uint2*>(sm + SM_A_HI + off) = make_uint2(hp0, hp1);
            *reinterpret_cast<uint2*>(sm + SM_A_LO + off) = make_uint2(lp0, lp1);
        }
    }

    // ldmatrix lane addressing (constant across iterations)
    int ar = lane & 15, ac8 = lane >> 4;                 // A: row within 16, k8-half
    int bg = lane >> 3;
    int bn = ((bg >> 1) << 3) + (lane & 7);              // B: n within 16
    int bk8 = bg & 1;                                    // B: k8-half
    uint32_t a_lane_off = (uint32_t)(wm * 32 + ar) * LDA_B + (uint32_t)ac8 * 16;
    uint32_t b_lane_off = (uint32_t)(wn * 32 + bn) * LDA_B + (uint32_t)bk8 * 16;

    for (int nb = 0; nb < NTILES; ++nb) {
        int col0 = nb * 64;
        __syncthreads();  // previous tile fully consumed / A ready on first iter
        // ---- B fill: 64 rows x 128 bf16 (hi+lo), contiguous global -> padded smem ----
#pragma unroll
        for (int p = 0; p < 4; ++p) {
            int idx = tid + p * 256;          // 0..1023
            int row = idx >> 4;               // 0..63
            int c8 = idx & 15;                // uint4 index (8 bf16)
            size_t gb = ((size_t)(col0 + row) * INDIM + c8 * 8);
            uint4 vh = *reinterpret_cast<const uint4*>(&g_Wt_hi[gb]);
            uint4 vl = *reinterpret_cast<const uint4*>(&g_Wt_lo[gb]);
            uint32_t off = (uint32_t)row * LDA_B + (uint32_t)c8 * 16;
            *reinterpret_cast<uint4*>(sm + SM_B_HI + off) = vh;
            *reinterpret_cast<uint4*>(sm + SM_B_LO + off) = vl;
        }
        __syncthreads();

        float acc[2][4][4];
#pragma unroll
        for (int mb = 0; mb < 2; ++mb)
#pragma unroll
            for (int jn = 0; jn < 4; ++jn)
#pragma unroll
                for (int r = 0; r < 4; ++r) acc[mb][jn][r] = 0.f;

#pragma unroll 2
        for (int kk = 0; kk < 8; ++kk) {
            uint32_t kbyte = (uint32_t)kk * 32;
            uint32_t ah[8], al[8], bh[8], bl[8];
            uint32_t aaddr0 = s_base + SM_A_HI + a_lane_off + kbyte;
            LDMX4(ah[0], ah[1], ah[2], ah[3], aaddr0);
            LDMX4(ah[4], ah[5], ah[6], ah[7], aaddr0 + 16 * LDA_B);
            uint32_t aaddr1 = s_base + SM_A_LO + a_lane_off + kbyte;
            LDMX4(al[0], al[1], al[2], al[3], aaddr1);
            LDMX4(al[4], al[5], al[6], al[7], aaddr1 + 16 * LDA_B);
            uint32_t baddr0 = s_base + SM_B_HI + b_lane_off + kbyte;
            LDMX4(bh[0], bh[1], bh[2], bh[3], baddr0);
            LDMX4(bh[4], bh[5], bh[6], bh[7], baddr0 + 16 * LDA_B);
            uint32_t baddr1 = s_base + SM_B_LO + b_lane_off + kbyte;
            LDMX4(bl[0], bl[1], bl[2], bl[3], baddr1);
            LDMX4(bl[4], bl[5], bl[6], bl[7], baddr1 + 16 * LDA_B);
#pragma unroll
            for (int mb = 0; mb < 2; ++mb) {
#pragma unroll
                for (int jn = 0; jn < 4; ++jn) {
                    MMA16816(acc[mb][jn], &ah[mb * 4], bh[jn * 2], bh[jn * 2 + 1]);
                    MMA16816(acc[mb][jn], &ah[mb * 4], bl[jn * 2], bl[jn * 2 + 1]);
                    MMA16816(acc[mb][jn], &al[mb * 4], bh[jn * 2], bh[jn * 2 + 1]);
                }
            }
        }

        // ---- epilogue: bias add + store float2 per (row, n8 block) ----
        int g = lane >> 2, t2 = (lane & 3) * 2;
        int sel = nb >> 2;  // 0=q 1=k 2=v 3=skip
#pragma unroll
        for (int mb = 0; mb < 2; ++mb) {
            int gr0 = row0 + wm * 32 + mb * 16 + g;
#pragma unroll
            for (int jn = 0; jn < 4; ++jn) {
                int gc = col0 + wn * 32 + jn * 8 + t2;
                float b0 = g_ball[gc], b1 = g_ball[gc + 1];
                float* outp;
                if (sel == 0)      outp = g_q    + (size_t)0 * 0 + (size_t)gc;
                else if (sel == 1) outp = g_k    + (size_t)(gc - 256);
                else if (sel == 2) outp = g_v    + (size_t)(gc - 512);
                else               outp = g_skip + (size_t)(gc - 768);
                size_t rstride = (sel == 3) ? HID : QKVDIM;
                if (gr0 < nrows) {
                    float2 o0 = make_float2(acc[mb][jn][0] + b0, acc[mb][jn][1] + b1);
                    *reinterpret_cast<float2*>(outp + (size_t)gr0 * rstride) = o0;
                }
                if (gr0 + 8 < nrows) {
                    float2 o1 = make_float2(acc[mb][jn][2] + b0, acc[mb][jn][3] + b1);
                    *reinterpret_cast<float2*>(outp + (size_t)(gr0 + 8) * rstride) = o1;
                }
            }
        }
    }
}

// ---------------- kernel: per-edge attention logits + segment max ----------------
__global__ void edge_logits_kernel(const int* __restrict__ ei, int E) {
    int gtid = blockIdx.x * blockDim.x + threadIdx.x;
    int e = gtid >> 5;
    if (e >= E) return;
    int l = gtid & 31;
    int src = ei[e], dst = ei[E + e];
    const float4* q4 = reinterpret_cast<const float4*>(g_q + (size_t)dst * QKVDIM);
    const float4* k4 = reinterpret_cast<const float4*>(g_k + (size_t)src * QKVDIM);
    float4 qa = q4[l],      ka = k4[l];
    float4 qb = q4[l + 32], kb = k4[l + 32];
    float acc1 = qa.x * ka.x + qa.y * ka.y + qa.z * ka.z + qa.w * ka.w;
    float acc2 = qb.x * kb.x + qb.y * kb.y + qb.z * kb.z + qb.w * kb.w;
#pragma unroll
    for (int m = 8; m > 0; m >>= 1) {
        acc1 += __shfl_xor_sync(0xFFFFFFFFu, acc1, m);
        acc2 += __shfl_xor_sync(0xFFFFFFFFu, acc2, m);
    }
    if ((l & 15) == 0) {
        int h = l >> 4;
        float a1 = acc1 * 0.125f;  // / sqrt(64)
        float a2 = acc2 * 0.125f;
        g_alpha[(size_t)e * 4 + h]     = a1;
        g_alpha[(size_t)e * 4 + h + 2] = a2;
        atomicMax(&g_menc[dst * 4 + h],     enc_f(a1));
        atomicMax(&g_menc[dst * 4 + h + 2], enc_f(a2));
    }
}

// ---------------- kernel: exp + segment sum ----------------
__global__ void exp_kernel(const int* __restrict__ ei, int E) {
    int i = blockIdx.x * blockDim.x + threadIdx.x;
    if (i >= E * 4) return;
    int e = i >> 2, h = i & 3;
    int dst = ei[E + e];
    float m = dec_f(g_menc[dst * 4 + h]);
    float ex = expf(g_alpha[i] - m);
    g_ex[i] = ex;
    atomicAdd(&g_denom[dst * 4 + h], ex);
}

// ---------------- kernel: weighted message scatter ----------------
__global__ void scatter_kernel(const int* __restrict__ ei, int E) {
    int gtid = blockIdx.x * blockDim.x + threadIdx.x;
    int e = gtid >> 5;
    if (e >= E) return;
    int l = gtid & 31;
    int src = ei[e], dst = ei[E + e];
    int h1 = l >> 4;
    float a1 = g_ex[(size_t)e * 4 + h1]     / (g_denom[dst * 4 + h1]     + 1e-16f);
    float a2 = g_ex[(size_t)e * 4 + h1 + 2] / (g_denom[dst * 4 + h1 + 2] + 1e-16f);
    const float4* v4 = reinterpret_cast<const float4*>(g_v + (size_t)src * QKVDIM);
    float4 va = v4[l], vb = v4[l + 32];
    float* dp = g_agg + (size_t)dst * QKVDIM + l * 4;
    red_add_v4(dp,       a1 * va.x, a1 * va.y, a1 * va.z, a1 * va.w);
    red_add_v4(dp + 128, a2 * vb.x, a2 * vb.y, a2 * vb.z, a2 * vb.w);
}

// ---------------- kernel: head mean + skip + tanh + MLP ----------------
__global__ void final_kernel(float* __restrict__ out, int n) {
    __shared__ float Wms[64][65];
    __shared__ float hs[4][64];
    int tid = threadIdx.x;
    for (int i = tid; i < 4096; i += 256) Wms[i >> 6][i & 63] = g_Wms[i];
    int node = blockIdx.x * 4 + (tid >> 6);
    int d = tid & 63;
    float hval = 0.f;
    if (node < n) {
        const float* ag = g_agg + (size_t)node * QKVDIM;
        float s = 0.25f * (ag[d] + ag[64 + d] + ag[128 + d] + ag[192 + d]) + g_skip[(size_t)node * HID + d];
        hval = tanhf(s);
    }
    hs[tid >> 6][d] = hval;
    __syncthreads();
    if (node < n) {
        int ni = tid >> 6;
        float acc = 0.f;
#pragma unroll 16
        for (int dd = 0; dd < 64; ++dd) acc += hs[ni][dd] * Wms[dd][d];
        out[(size_t)node * OUTD + d] = acc;
    }
}

// ---------------- launch ----------------
extern "C" void kernel_launch(void* const* d_in, const int* in_sizes, int n_in,
                              void* d_out, int out_size) {
    const float* x     = (const float*)d_in[0];
    const int*   ei    = (const int*)  d_in[1];
    const float* Wq    = (const float*)d_in[2];
    const float* bq    = (const float*)d_in[3];
    const float* Wk    = (const float*)d_in[4];
    const float* bk    = (const float*)d_in[5];
    const float* Wv    = (const float*)d_in[6];
    const float* bv    = (const float*)d_in[7];
    const float* Wskip = (const float*)d_in[8];
    const float* bskip = (const float*)d_in[9];
    const float* Wmlp  = (const float*)d_in[10];
    float* out = (float*)d_out;

    int N = in_sizes[0] / INDIM;
    int E = in_sizes[1] / 2;

    cudaFuncSetAttribute(gemm_mma_kernel, cudaFuncAttributeMaxDynamicSharedMemorySize,
                         GEMM_SMEM_BYTES);

    prep_kernel<<<(COLS_ALL * INDIM + 255) / 256, 256>>>(Wq, bq, Wk, bk, Wv, bv, Wskip, bskip);
    sigma_kernel<<<1, 64>>>(Wmlp);
    init_kernel<<<(N * 64 + 255) / 256, 256>>>(N);

    int mblocks = (N + 127) / 128;
    gemm_mma_kernel<<<mblocks, 256, GEMM_SMEM_BYTES>>>(x, N);

    int eb = (E * 32 + 255) / 256;
    edge_logits_kernel<<<eb, 256>>>(ei, E);
    exp_kernel<<<(E * 4 + 255) / 256, 256>>>(ei, E);
    scatter_kernel<<<eb, 256>>>(ei, E);
    final_kernel<<<(N + 3) / 4, 256>>>(out, N);
}

// round 4
// speedup vs baseline: 1.5334x; 1.0505x over previous
#include <cuda_runtime.h>
#include <cuda_bf16.h>
#include <math.h>
#include <stdint.h>

// Problem constants
#define NMAX 50000
#define EMAX 300000
#define INDIM 128
#define HID 64
#define HEADS 4
#define QKVDIM 256      // HEADS*HID
#define COLS_ALL 832    // 3*256 + 64 (Wq|Wk|Wv|Wskip)
#define OUTD 64
#define NTILES 13       // 832 / 64

// ---------------- scratch (static device globals; no runtime alloc) ----------------
__device__ float g_ball[COLS_ALL];
__device__ __nv_bfloat16 g_Wt_hi[COLS_ALL * INDIM];
__device__ __nv_bfloat16 g_Wt_lo[COLS_ALL * INDIM];
__device__ float g_q[(size_t)NMAX * QKVDIM];
__device__ float g_k[(size_t)NMAX * QKVDIM];
__device__ float g_v[(size_t)NMAX * QKVDIM];
__device__ float g_skip[(size_t)NMAX * HID];
__device__ float g_hidden[(size_t)NMAX * HID];
__device__ float g_Wms[HID * OUTD];
// CSR scratch
__device__ int g_deg[NMAX];
__device__ int g_cursor[NMAX];
__device__ int g_rowstart[NMAX + 1];
__device__ int g_esrc[EMAX];

// ---------------- helpers ----------------
__device__ __forceinline__ uint32_t smem_u32(const void* p) {
    uint32_t a;
    asm("{ .reg .u64 t; cvta.to.shared.u64 t, %1; cvt.u32.u64 %0, t; }" : "=r"(a) : "l"(p));
    return a;
}

#define LDMX4(r0, r1, r2, r3, addr) \
    asm volatile("ldmatrix.sync.aligned.m8n8.x4.shared.b16 {%0,%1,%2,%3}, [%4];" \
                 : "=r"(r0), "=r"(r1), "=r"(r2), "=r"(r3) : "r"(addr))

#define MMA16816(d, a, b0, b1) \
    asm volatile("mma.sync.aligned.m16n8k16.row.col.f32.bf16.bf16.f32 " \
                 "{%0,%1,%2,%3},{%4,%5,%6,%7},{%8,%9},{%0,%1,%2,%3};" \
                 : "+f"((d)[0]), "+f"((d)[1]), "+f"((d)[2]), "+f"((d)[3]) \
                 : "r"((a)[0]), "r"((a)[1]), "r"((a)[2]), "r"((a)[3]), "r"(b0), "r"(b1))

// ---------------- kernel: pack weights (transposed hi/lo bf16) + biases ----------------
__global__ void prep_kernel(const float* __restrict__ Wq, const float* __restrict__ bq,
                            const float* __restrict__ Wk, const float* __restrict__ bk,
                            const float* __restrict__ Wv, const float* __restrict__ bv,
                            const float* __restrict__ Ws, const float* __restrict__ bs) {
    int i = blockIdx.x * blockDim.x + threadIdx.x;
    if (i < COLS_ALL) {
        float b = (i < 256) ? bq[i] : (i < 512) ? bk[i - 256] : (i < 768) ? bv[i - 512] : bs[i - 768];
        g_ball[i] = b;
    }
    if (i < COLS_ALL * INDIM) {
        int n = i / INDIM, k = i % INDIM;
        float w = (n < 256) ? Wq[k * 256 + n]
                : (n < 512) ? Wk[k * 256 + (n - 256)]
                : (n < 768) ? Wv[k * 256 + (n - 512)]
                :             Ws[k * 64  + (n - 768)];
        __nv_bfloat16 hi = __float2bfloat16(w);
        __nv_bfloat16 lo = __float2bfloat16(w - __bfloat162float(hi));
        g_Wt_hi[i] = hi;
        g_Wt_lo[i] = lo;
    }
}

// ---------------- kernel: spectral norm power iteration (exact replica) ----------------
__global__ void sigma_kernel(const float* __restrict__ Wmlp) {
    __shared__ float Wsh[64][65];
    __shared__ float u[64], vv[64], upre[64], red[64];
    int t = threadIdx.x;
    for (int i = 0; i < 64; ++i) Wsh[i][t] = Wmlp[i * 64 + t];
    u[t] = 0.125f;
    __syncthreads();
    for (int it = 0; it < 20; ++it) {
        float s = 0.f;
        for (int i = 0; i < 64; ++i) s += Wsh[i][t] * u[i];
        red[t] = s * s; __syncthreads();
        for (int off = 32; off > 0; off >>= 1) { if (t < off) red[t] += red[t + off]; __syncthreads(); }
        float nv = sqrtf(red[0]);
        vv[t] = s / (nv + 1e-12f);
        __syncthreads();
        float s2 = 0.f;
        for (int j = 0; j < 64; ++j) s2 += Wsh[t][j] * vv[j];
        upre[t] = s2;
        red[t] = s2 * s2; __syncthreads();
        for (int off = 32; off > 0; off >>= 1) { if (t < off) red[t] += red[t + off]; __syncthreads(); }
        float nu = sqrtf(red[0]);
        u[t] = s2 / (nu + 1e-12f);
        __syncthreads();
    }
    red[t] = u[t] * upre[t]; __syncthreads();
    for (int off = 32; off > 0; off >>= 1) { if (t < off) red[t] += red[t + off]; __syncthreads(); }
    float sigma = red[0];
    for (int j = 0; j < 64; ++j) g_Wms[t * 64 + j] = Wsh[t][j] / sigma;
}

// ---------------- CSR build ----------------
__global__ void zero_kernel(int n) {
    int i = blockIdx.x * blockDim.x + threadIdx.x;
    if (i < n) { g_deg[i] = 0; g_cursor[i] = 0; }
}
__global__ void hist_kernel(const int* __restrict__ ei, int E) {
    int e = blockIdx.x * blockDim.x + threadIdx.x;
    if (e < E) atomicAdd(&g_deg[ei[E + e]], 1);
}
__global__ void scan_kernel(int n) {
    __shared__ int s[1024];
    int t = threadIdx.x;
    int chunk = (n + 1023) >> 10;
    int lo = t * chunk, hi = min(lo + chunk, n);
    int sum = 0;
    for (int i = lo; i < hi; ++i) sum += g_deg[i];
    s[t] = sum; __syncthreads();
    for (int off = 1; off < 1024; off <<= 1) {
        int v = (t >= off) ? s[t - off] : 0;
        __syncthreads();
        if (t >= off) s[t] += v;
        __syncthreads();
    }
    int run = (t == 0) ? 0 : s[t - 1];
    for (int i = lo; i < hi; ++i) { g_rowstart[i] = run; run += g_deg[i]; }
    if (lo < n && hi == n) g_rowstart[n] = run;
}
__global__ void scatter_edges_kernel(const int* __restrict__ ei, int E) {
    int e = blockIdx.x * blockDim.x + threadIdx.x;
    if (e >= E) return;
    int dst = ei[E + e];
    int pos = g_rowstart[dst] + atomicAdd(&g_cursor[dst], 1);
    g_esrc[pos] = ei[e];
}

// ---------------- bf16 mma.sync projection GEMM: [N,128] x [128,832] ----------------
#define LDA_E 136
#define LDA_B 272
#define SM_A_HI 0
#define SM_A_LO 34816
#define SM_B_HI 69632
#define SM_B_LO 87040
#define GEMM_SMEM_BYTES 104448

__global__ void __launch_bounds__(256) gemm_mma_kernel(const float* __restrict__ x, int nrows) {
    extern __shared__ __align__(16) char sm[];
    const uint32_t s_base = smem_u32(sm);

    int tid = threadIdx.x;
    int lane = tid & 31;
    int wid = tid >> 5;
    int wm = wid & 3;
    int wn = wid >> 2;
    int row0 = blockIdx.x * 128;

    // ---- A fill: 128x128 fp32 -> bf16 hi/lo into padded smem ----
    {
#pragma unroll
        for (int p = 0; p < 16; ++p) {
            int idx = tid + p * 256;
            int row = idx >> 5;
            int c4 = idx & 31;
            int gr = row0 + row;
            float4 v = make_float4(0.f, 0.f, 0.f, 0.f);
            if (gr < nrows) v = *reinterpret_cast<const float4*>(x + (size_t)gr * INDIM + c4 * 4);
            __nv_bfloat16 h0 = __float2bfloat16(v.x), h1 = __float2bfloat16(v.y);
            __nv_bfloat16 h2 = __float2bfloat16(v.z), h3 = __float2bfloat16(v.w);
            __nv_bfloat16 l0 = __float2bfloat16(v.x - __bfloat162float(h0));
            __nv_bfloat16 l1 = __float2bfloat16(v.y - __bfloat162float(h1));
            __nv_bfloat16 l2 = __float2bfloat16(v.z - __bfloat162float(h2));
            __nv_bfloat16 l3 = __float2bfloat16(v.w - __bfloat162float(h3));
            uint32_t hp0 = ((uint32_t)*(unsigned short*)&h1 << 16) | *(unsigned short*)&h0;
            uint32_t hp1 = ((uint32_t)*(unsigned short*)&h3 << 16) | *(unsigned short*)&h2;
            uint32_t lp0 = ((uint32_t)*(unsigned short*)&l1 << 16) | *(unsigned short*)&l0;
            uint32_t lp1 = ((uint32_t)*(unsigned short*)&l3 << 16) | *(unsigned short*)&l2;
            uint32_t off = (uint32_t)row * LDA_B + (uint32_t)c4 * 8;
            *reinterpret_cast<uint2*>(sm + SM_A_HI + off) = make_uint2(hp0, hp1);
            *reinterpret_cast<uint2*>(sm + SM_A_LO + off) = make_uint2(lp0, lp1);
        }
    }

    int ar = lane & 15, ac8 = lane >> 4;
    int bg = lane >> 3;
    int bn = ((bg >> 1) << 3) + (lane & 7);
    int bk8 = bg & 1;
    uint32_t a_lane_off = (uint32_t)(wm * 32 + ar) * LDA_B + (uint32_t)ac8 * 16;
    uint32_t b_lane_off = (uint32_t)(wn * 32 + bn) * LDA_B + (uint32_t)bk8 * 16;

    for (int nb = 0; nb < NTILES; ++nb) {
        int col0 = nb * 64;
        __syncthreads();
#pragma unroll
        for (int p = 0; p < 4; ++p) {
            int idx = tid + p * 256;
            int row = idx >> 4;
            int c8 = idx & 15;
            size_t gb = ((size_t)(col0 + row) * INDIM + c8 * 8);
            uint4 vh = *reinterpret_cast<const uint4*>(&g_Wt_hi[gb]);
            uint4 vl = *reinterpret_cast<const uint4*>(&g_Wt_lo[gb]);
            uint32_t off = (uint32_t)row * LDA_B + (uint32_t)c8 * 16;
            *reinterpret_cast<uint4*>(sm + SM_B_HI + off) = vh;
            *reinterpret_cast<uint4*>(sm + SM_B_LO + off) = vl;
        }
        __syncthreads();

        float acc[2][4][4];
#pragma unroll
        for (int mb = 0; mb < 2; ++mb)
#pragma unroll
            for (int jn = 0; jn < 4; ++jn)
#pragma unroll
                for (int r = 0; r < 4; ++r) acc[mb][jn][r] = 0.f;

#pragma unroll 2
        for (int kk = 0; kk < 8; ++kk) {
            uint32_t kbyte = (uint32_t)kk * 32;
            uint32_t ah[8], al[8], bh[8], bl[8];
            uint32_t aaddr0 = s_base + SM_A_HI + a_lane_off + kbyte;
            LDMX4(ah[0], ah[1], ah[2], ah[3], aaddr0);
            LDMX4(ah[4], ah[5], ah[6], ah[7], aaddr0 + 16 * LDA_B);
            uint32_t aaddr1 = s_base + SM_A_LO + a_lane_off + kbyte;
            LDMX4(al[0], al[1], al[2], al[3], aaddr1);
            LDMX4(al[4], al[5], al[6], al[7], aaddr1 + 16 * LDA_B);
            uint32_t baddr0 = s_base + SM_B_HI + b_lane_off + kbyte;
            LDMX4(bh[0], bh[1], bh[2], bh[3], baddr0);
            LDMX4(bh[4], bh[5], bh[6], bh[7], baddr0 + 16 * LDA_B);
            uint32_t baddr1 = s_base + SM_B_LO + b_lane_off + kbyte;
            LDMX4(bl[0], bl[1], bl[2], bl[3], baddr1);
            LDMX4(bl[4], bl[5], bl[6], bl[7], baddr1 + 16 * LDA_B);
#pragma unroll
            for (int mb = 0; mb < 2; ++mb) {
#pragma unroll
                for (int jn = 0; jn < 4; ++jn) {
                    MMA16816(acc[mb][jn], &ah[mb * 4], bh[jn * 2], bh[jn * 2 + 1]);
                    MMA16816(acc[mb][jn], &ah[mb * 4], bl[jn * 2], bl[jn * 2 + 1]);
                    MMA16816(acc[mb][jn], &al[mb * 4], bh[jn * 2], bh[jn * 2 + 1]);
                }
            }
        }

        int g = lane >> 2, t2 = (lane & 3) * 2;
        int sel = nb >> 2;
#pragma unroll
        for (int mb = 0; mb < 2; ++mb) {
            int gr0 = row0 + wm * 32 + mb * 16 + g;
#pragma unroll
            for (int jn = 0; jn < 4; ++jn) {
                int gc = col0 + wn * 32 + jn * 8 + t2;
                float b0 = g_ball[gc], b1 = g_ball[gc + 1];
                float* outp;
                if (sel == 0)      outp = g_q    + (size_t)gc;
                else if (sel == 1) outp = g_k    + (size_t)(gc - 256);
                else if (sel == 2) outp = g_v    + (size_t)(gc - 512);
                else               outp = g_skip + (size_t)(gc - 768);
                size_t rstride = (sel == 3) ? HID : QKVDIM;
                if (gr0 < nrows) {
                    float2 o0 = make_float2(acc[mb][jn][0] + b0, acc[mb][jn][1] + b1);
                    *reinterpret_cast<float2*>(outp + (size_t)gr0 * rstride) = o0;
                }
                if (gr0 + 8 < nrows) {
                    float2 o1 = make_float2(acc[mb][jn][2] + b0, acc[mb][jn][3] + b1);
                    *reinterpret_cast<float2*>(outp + (size_t)(gr0 + 8) * rstride) = o1;
                }
            }
        }
    }
}

// ---------------- fused attention: warp per dst node, online softmax ----------------
// lane l owns dims (l&15)*4..+3 of head (l>>4) [slot a] and head (l>>4)+2 [slot b].
__global__ void __launch_bounds__(256) attn_kernel(int n) {
    int gw = (blockIdx.x * blockDim.x + threadIdx.x) >> 5;
    if (gw >= n) return;
    int lane = threadIdx.x & 31;
    int node = gw;

    const float4* q4 = reinterpret_cast<const float4*>(g_q + (size_t)node * QKVDIM);
    float4 qa = q4[lane], qb = q4[lane + 32];

    int start = g_rowstart[node], end = g_rowstart[node + 1];
    float m1 = -INFINITY, m2 = -INFINITY;
    float d1 = 0.f, d2 = 0.f;
    float4 Sa = make_float4(0.f, 0.f, 0.f, 0.f);
    float4 Sb = make_float4(0.f, 0.f, 0.f, 0.f);

    for (int p = start; p < end; ++p) {
        int src = g_esrc[p];
        const float4* k4 = reinterpret_cast<const float4*>(g_k + (size_t)src * QKVDIM);
        const float4* v4 = reinterpret_cast<const float4*>(g_v + (size_t)src * QKVDIM);
        float4 ka = k4[lane], kb = k4[lane + 32];
        float t1 = qa.x * ka.x + qa.y * ka.y + qa.z * ka.z + qa.w * ka.w;
        float t2 = qb.x * kb.x + qb.y * kb.y + qb.z * kb.z + qb.w * kb.w;
#pragma unroll
        for (int mm = 8; mm > 0; mm >>= 1) {
            t1 += __shfl_xor_sync(0xFFFFFFFFu, t1, mm);
            t2 += __shfl_xor_sync(0xFFFFFFFFu, t2, mm);
        }
        float a1 = t1 * 0.125f;   // / sqrt(64)
        float a2 = t2 * 0.125f;
        float4 va = v4[lane], vb = v4[lane + 32];
        float nm1 = fmaxf(m1, a1), nm2 = fmaxf(m2, a2);
        float s1 = __expf(m1 - nm1), s2 = __expf(m2 - nm2);  // exp(-inf)=0 first iter
        float e1 = __expf(a1 - nm1), e2 = __expf(a2 - nm2);
        d1 = d1 * s1 + e1;
        d2 = d2 * s2 + e2;
        Sa.x = Sa.x * s1 + e1 * va.x; Sa.y = Sa.y * s1 + e1 * va.y;
        Sa.z = Sa.z * s1 + e1 * va.z; Sa.w = Sa.w * s1 + e1 * va.w;
        Sb.x = Sb.x * s2 + e2 * vb.x; Sb.y = Sb.y * s2 + e2 * vb.y;
        Sb.z = Sb.z * s2 + e2 * vb.z; Sb.w = Sb.w * s2 + e2 * vb.w;
        m1 = nm1; m2 = nm2;
    }

    float r1 = 1.f / (d1 + 1e-16f);
    float r2 = 1.f / (d2 + 1e-16f);
    float4 A;
    A.x = Sa.x * r1 + Sb.x * r2;
    A.y = Sa.y * r1 + Sb.y * r2;
    A.z = Sa.z * r1 + Sb.z * r2;
    A.w = Sa.w * r1 + Sb.w * r2;
    // add the other two heads (held by lane^16, same dims)
    A.x += __shfl_xor_sync(0xFFFFFFFFu, A.x, 16);
    A.y += __shfl_xor_sync(0xFFFFFFFFu, A.y, 16);
    A.z += __shfl_xor_sync(0xFFFFFFFFu, A.z, 16);
    A.w += __shfl_xor_sync(0xFFFFFFFFu, A.w, 16);

    if (lane < 16) {
        float4 sk = *reinterpret_cast<const float4*>(g_skip + (size_t)node * HID + lane * 4);
        float4 h;
        h.x = tanhf(0.25f * A.x + sk.x);
        h.y = tanhf(0.25f * A.y + sk.y);
        h.z = tanhf(0.25f * A.z + sk.z);
        h.w = tanhf(0.25f * A.w + sk.w);
        *reinterpret_cast<float4*>(g_hidden + (size_t)node * HID + lane * 4) = h;
    }
}

// ---------------- kernel: MLP matvec out = hidden @ Wms ----------------
__global__ void final_kernel(float* __restrict__ out, int n) {
    __shared__ float Wms[64][65];
    __shared__ float hs[4][64];
    int tid = threadIdx.x;
    for (int i = tid; i < 4096; i += 256) Wms[i >> 6][i & 63] = g_Wms[i];
    int node = blockIdx.x * 4 + (tid >> 6);
    int d = tid & 63;
    hs[tid >> 6][d] = (node < n) ? g_hidden[(size_t)node * HID + d] : 0.f;
    __syncthreads();
    if (node < n) {
        int ni = tid >> 6;
        float acc = 0.f;
#pragma unroll 16
        for (int dd = 0; dd < 64; ++dd) acc += hs[ni][dd] * Wms[dd][d];
        out[(size_t)node * OUTD + d] = acc;
    }
}

// ---------------- launch ----------------
extern "C" void kernel_launch(void* const* d_in, const int* in_sizes, int n_in,
                              void* d_out, int out_size) {
    const float* x     = (const float*)d_in[0];
    const int*   ei    = (const int*)  d_in[1];
    const float* Wq    = (const float*)d_in[2];
    const float* bq    = (const float*)d_in[3];
    const float* Wk    = (const float*)d_in[4];
    const float* bk    = (const float*)d_in[5];
    const float* Wv    = (const float*)d_in[6];
    const float* bv    = (const float*)d_in[7];
    const float* Wskip = (const float*)d_in[8];
    const float* bskip = (const float*)d_in[9];
    const float* Wmlp  = (const float*)d_in[10];
    float* out = (float*)d_out;

    int N = in_sizes[0] / INDIM;
    int E = in_sizes[1] / 2;

    cudaFuncSetAttribute(gemm_mma_kernel, cudaFuncAttributeMaxDynamicSharedMemorySize,
                         GEMM_SMEM_BYTES);

    // CSR build (independent of projections)
    zero_kernel<<<(N + 255) / 256, 256>>>(N);
    hist_kernel<<<(E + 255) / 256, 256>>>(ei, E);
    scan_kernel<<<1, 1024>>>(N);
    scatter_edges_kernel<<<(E + 255) / 256, 256>>>(ei, E);

    // projections
    prep_kernel<<<(COLS_ALL * INDIM + 255) / 256, 256>>>(Wq, bq, Wk, bk, Wv, bv, Wskip, bskip);
    sigma_kernel<<<1, 64>>>(Wmlp);
    int mblocks = (N + 127) / 128;
    gemm_mma_kernel<<<mblocks, 256, GEMM_SMEM_BYTES>>>(x, N);

    // fused attention + epilogue
    attn_kernel<<<(N * 32 + 255) / 256, 256>>>(N);
    final_kernel<<<(N + 3) / 4, 256>>>(out, N);
}

// round 5
// speedup vs baseline: 2.0244x; 1.3202x over previous
#include <cuda_runtime.h>
#include <cuda_fp16.h>
#include <math.h>
#include <stdint.h>

// Problem constants
#define NMAX 50000
#define EMAX 300000
#define INDIM 128
#define HID 64
#define HEADS 4
#define QKVDIM 256      // HEADS*HID
#define COLS_ALL 832    // 3*256 + 64 (Wq|Wk|Wv|Wskip)
#define OUTD 64
#define NTILES 13       // 832 / 64

// ---------------- scratch (static device globals; no runtime alloc) ----------------
__device__ float g_ball[COLS_ALL];
__device__ __align__(16) __half g_Wt_h[COLS_ALL * INDIM];   // [n][k] transposed weights fp16
__device__ float g_q[(size_t)NMAX * QKVDIM];
__device__ __align__(16) __half g_kvh[(size_t)NMAX * 512];  // per node: k[256] | v[256] fp16
__device__ float g_skip[(size_t)NMAX * HID];
__device__ float g_Wms[HID * OUTD];
// CSR scratch
__device__ int g_deg[NMAX];
__device__ int g_cursor[NMAX];
__device__ int g_rowstart[NMAX + 1];
__device__ int g_esrc[EMAX];

// ---------------- helpers ----------------
__device__ __forceinline__ uint32_t smem_u32(const void* p) {
    uint32_t a;
    asm("{ .reg .u64 t; cvta.to.shared.u64 t, %1; cvt.u32.u64 %0, t; }" : "=r"(a) : "l"(p));
    return a;
}

#define LDMX4(r0, r1, r2, r3, addr) \
    asm volatile("ldmatrix.sync.aligned.m8n8.x4.shared.b16 {%0,%1,%2,%3}, [%4];" \
                 : "=r"(r0), "=r"(r1), "=r"(r2), "=r"(r3) : "r"(addr))

#define MMA16816H(d, a, b0, b1) \
    asm volatile("mma.sync.aligned.m16n8k16.row.col.f32.f16.f16.f32 " \
                 "{%0,%1,%2,%3},{%4,%5,%6,%7},{%8,%9},{%0,%1,%2,%3};" \
                 : "+f"((d)[0]), "+f"((d)[1]), "+f"((d)[2]), "+f"((d)[3]) \
                 : "r"((a)[0]), "r"((a)[1]), "r"((a)[2]), "r"((a)[3]), "r"(b0), "r"(b1))

__device__ __forceinline__ uint32_t h2bits(__half2 h) { return *reinterpret_cast<uint32_t*>(&h); }

// ---------------- kernel: pack weights (transposed fp16) + biases ----------------
__global__ void prep_kernel(const float* __restrict__ Wq, const float* __restrict__ bq,
                            const float* __restrict__ Wk, const float* __restrict__ bk,
                            const float* __restrict__ Wv, const float* __restrict__ bv,
                            const float* __restrict__ Ws, const float* __restrict__ bs) {
    int i = blockIdx.x * blockDim.x + threadIdx.x;
    if (i < COLS_ALL) {
        float b = (i < 256) ? bq[i] : (i < 512) ? bk[i - 256] : (i < 768) ? bv[i - 512] : bs[i - 768];
        g_ball[i] = b;
    }
    if (i < COLS_ALL * INDIM) {
        int n = i / INDIM, k = i % INDIM;
        float w = (n < 256) ? Wq[k * 256 + n]
                : (n < 512) ? Wk[k * 256 + (n - 256)]
                : (n < 768) ? Wv[k * 256 + (n - 512)]
                :             Ws[k * 64  + (n - 768)];
        g_Wt_h[i] = __float2half_rn(w);
    }
}

// ---------------- kernel: spectral norm power iteration (exact replica) ----------------
__global__ void sigma_kernel(const float* __restrict__ Wmlp) {
    __shared__ float Wsh[64][65];
    __shared__ float u[64], vv[64], upre[64], red[64];
    int t = threadIdx.x;
    for (int i = 0; i < 64; ++i) Wsh[i][t] = Wmlp[i * 64 + t];
    u[t] = 0.125f;
    __syncthreads();
    for (int it = 0; it < 20; ++it) {
        float s = 0.f;
        for (int i = 0; i < 64; ++i) s += Wsh[i][t] * u[i];
        red[t] = s * s; __syncthreads();
        for (int off = 32; off > 0; off >>= 1) { if (t < off) red[t] += red[t + off]; __syncthreads(); }
        float nv = sqrtf(red[0]);
        vv[t] = s / (nv + 1e-12f);
        __syncthreads();
        float s2 = 0.f;
        for (int j = 0; j < 64; ++j) s2 += Wsh[t][j] * vv[j];
        upre[t] = s2;
        red[t] = s2 * s2; __syncthreads();
        for (int off = 32; off > 0; off >>= 1) { if (t < off) red[t] += red[t + off]; __syncthreads(); }
        float nu = sqrtf(red[0]);
        u[t] = s2 / (nu + 1e-12f);
        __syncthreads();
    }
    red[t] = u[t] * upre[t]; __syncthreads();
    for (int off = 32; off > 0; off >>= 1) { if (t < off) red[t] += red[t + off]; __syncthreads(); }
    float sigma = red[0];
    for (int j = 0; j < 64; ++j) g_Wms[t * 64 + j] = Wsh[t][j] / sigma;
}

// ---------------- CSR build ----------------
__global__ void zero_kernel(int n) {
    int i = blockIdx.x * blockDim.x + threadIdx.x;
    if (i < n) { g_deg[i] = 0; g_cursor[i] = 0; }
}
__global__ void hist_kernel(const int* __restrict__ ei, int E) {
    int e = blockIdx.x * blockDim.x + threadIdx.x;
    if (e < E) atomicAdd(&g_deg[ei[E + e]], 1);
}
__global__ void scan_kernel(int n) {
    __shared__ int s[1024];
    int t = threadIdx.x;
    int chunk = (n + 1023) >> 10;
    int lo = t * chunk, hi = min(lo + chunk, n);
    int sum = 0;
    for (int i = lo; i < hi; ++i) sum += g_deg[i];
    s[t] = sum; __syncthreads();
    for (int off = 1; off < 1024; off <<= 1) {
        int v = (t >= off) ? s[t - off] : 0;
        __syncthreads();
        if (t >= off) s[t] += v;
        __syncthreads();
    }
    int run = (t == 0) ? 0 : s[t - 1];
    for (int i = lo; i < hi; ++i) { g_rowstart[i] = run; run += g_deg[i]; }
    if (lo < n && hi == n) g_rowstart[n] = run;
}
__global__ void scatter_edges_kernel(const int* __restrict__ ei, int E) {
    int e = blockIdx.x * blockDim.x + threadIdx.x;
    if (e >= E) return;
    int dst = ei[E + e];
    int pos = g_rowstart[dst] + atomicAdd(&g_cursor[dst], 1);
    g_esrc[pos] = ei[e];
}

// ---------------- fp16 2-pass mma.sync projection GEMM: [N,128] x [128,832] ----------------
// acc = Ahi*B + Alo*B (A split fp16 hi/lo, B single fp16). Residual err = A*Blo ~1.4e-4.
#define LDA_B 272
#define SM_A_HI 0
#define SM_A_LO 34816
#define SM_B 69632
#define GEMM_SMEM_BYTES 87040

__global__ void __launch_bounds__(256) gemm_mma_kernel(const float* __restrict__ x, int nrows) {
    extern __shared__ __align__(16) char sm[];
    const uint32_t s_base = smem_u32(sm);

    int tid = threadIdx.x;
    int lane = tid & 31;
    int wid = tid >> 5;
    int wm = wid & 3;
    int wn = wid >> 2;
    int row0 = blockIdx.x * 128;

    // ---- A fill: 128x128 fp32 -> fp16 hi/lo into padded smem ----
    {
#pragma unroll
        for (int p = 0; p < 16; ++p) {
            int idx = tid + p * 256;
            int row = idx >> 5;
            int c4 = idx & 31;
            int gr = row0 + row;
            float4 v = make_float4(0.f, 0.f, 0.f, 0.f);
            if (gr < nrows) v = *reinterpret_cast<const float4*>(x + (size_t)gr * INDIM + c4 * 4);
            __half h0 = __float2half_rn(v.x), h1 = __float2half_rn(v.y);
            __half h2 = __float2half_rn(v.z), h3 = __float2half_rn(v.w);
            __half l0 = __float2half_rn(v.x - __half2float(h0));
            __half l1 = __float2half_rn(v.y - __half2float(h1));
            __half l2 = __float2half_rn(v.z - __half2float(h2));
            __half l3 = __float2half_rn(v.w - __half2float(h3));
            uint32_t hp0 = ((uint32_t)*(unsigned short*)&h1 << 16) | *(unsigned short*)&h0;
            uint32_t hp1 = ((uint32_t)*(unsigned short*)&h3 << 16) | *(unsigned short*)&h2;
            uint32_t lp0 = ((uint32_t)*(unsigned short*)&l1 << 16) | *(unsigned short*)&l0;
            uint32_t lp1 = ((uint32_t)*(unsigned short*)&l3 << 16) | *(unsigned short*)&l2;
            uint32_t off = (uint32_t)row * LDA_B + (uint32_t)c4 * 8;
            *reinterpret_cast<uint2*>(sm + SM_A_HI + off) = make_uint2(hp0, hp1);
            *reinterpret_cast<uint2*>(sm + SM_A_LO + off) = make_uint2(lp0, lp1);
        }
    }

    int ar = lane & 15, ac8 = lane >> 4;
    int bg = lane >> 3;
    int bn = ((bg >> 1) << 3) + (lane & 7);
    int bk8 = bg & 1;
    uint32_t a_lane_off = (uint32_t)(wm * 32 + ar) * LDA_B + (uint32_t)ac8 * 16;
    uint32_t b_lane_off = (uint32_t)(wn * 32 + bn) * LDA_B + (uint32_t)bk8 * 16;

    for (int nb = 0; nb < NTILES; ++nb) {
        int col0 = nb * 64;
        __syncthreads();
        // ---- B fill: 64 rows x 128 fp16 ----
#pragma unroll
        for (int p = 0; p < 4; ++p) {
            int idx = tid + p * 256;
            int row = idx >> 4;
            int c8 = idx & 15;
            size_t gb = ((size_t)(col0 + row) * INDIM + c8 * 8);
            uint4 vh = *reinterpret_cast<const uint4*>(&g_Wt_h[gb]);
            uint32_t off = (uint32_t)row * LDA_B + (uint32_t)c8 * 16;
            *reinterpret_cast<uint4*>(sm + SM_B + off) = vh;
        }
        __syncthreads();

        float acc[2][4][4];
#pragma unroll
        for (int mb = 0; mb < 2; ++mb)
#pragma unroll
            for (int jn = 0; jn < 4; ++jn)
#pragma unroll
                for (int r = 0; r < 4; ++r) acc[mb][jn][r] = 0.f;

#pragma unroll 2
        for (int kk = 0; kk < 8; ++kk) {
            uint32_t kbyte = (uint32_t)kk * 32;
            uint32_t ah[8], al[8], bb[8];
            uint32_t aaddr0 = s_base + SM_A_HI + a_lane_off + kbyte;
            LDMX4(ah[0], ah[1], ah[2], ah[3], aaddr0);
            LDMX4(ah[4], ah[5], ah[6], ah[7], aaddr0 + 16 * LDA_B);
            uint32_t aaddr1 = s_base + SM_A_LO + a_lane_off + kbyte;
            LDMX4(al[0], al[1], al[2], al[3], aaddr1);
            LDMX4(al[4], al[5], al[6], al[7], aaddr1 + 16 * LDA_B);
            uint32_t baddr0 = s_base + SM_B + b_lane_off + kbyte;
            LDMX4(bb[0], bb[1], bb[2], bb[3], baddr0);
            LDMX4(bb[4], bb[5], bb[6], bb[7], baddr0 + 16 * LDA_B);
#pragma unroll
            for (int mb = 0; mb < 2; ++mb) {
#pragma unroll
                for (int jn = 0; jn < 4; ++jn) {
                    MMA16816H(acc[mb][jn], &ah[mb * 4], bb[jn * 2], bb[jn * 2 + 1]);
                    MMA16816H(acc[mb][jn], &al[mb * 4], bb[jn * 2], bb[jn * 2 + 1]);
                }
            }
        }

        int g = lane >> 2, t2 = (lane & 3) * 2;
        int sel = nb >> 2;  // 0=q 1=k 2=v 3=skip
#pragma unroll
        for (int mb = 0; mb < 2; ++mb) {
            int gr0 = row0 + wm * 32 + mb * 16 + g;
#pragma unroll
            for (int jn = 0; jn < 4; ++jn) {
                int gc = col0 + wn * 32 + jn * 8 + t2;
                float b0 = g_ball[gc], b1 = g_ball[gc + 1];
                float v00 = acc[mb][jn][0] + b0, v01 = acc[mb][jn][1] + b1;
                float v10 = acc[mb][jn][2] + b0, v11 = acc[mb][jn][3] + b1;
                if (sel == 0) {
                    if (gr0 < nrows)
                        *reinterpret_cast<float2*>(g_q + (size_t)gr0 * QKVDIM + gc) = make_float2(v00, v01);
                    if (gr0 + 8 < nrows)
                        *reinterpret_cast<float2*>(g_q + (size_t)(gr0 + 8) * QKVDIM + gc) = make_float2(v10, v11);
                } else if (sel == 3) {
                    int sc = gc - 768;
                    if (gr0 < nrows)
                        *reinterpret_cast<float2*>(g_skip + (size_t)gr0 * HID + sc) = make_float2(v00, v01);
                    if (gr0 + 8 < nrows)
                        *reinterpret_cast<float2*>(g_skip + (size_t)(gr0 + 8) * HID + sc) = make_float2(v10, v11);
                } else {
                    // k at [0,256), v at [256,512): both map to gc-256
                    int koff = gc - 256;
                    if (gr0 < nrows)
                        *reinterpret_cast<__half2*>(&g_kvh[(size_t)gr0 * 512 + koff]) = __floats2half2_rn(v00, v01);
                    if (gr0 + 8 < nrows)
                        *reinterpret_cast<__half2*>(&g_kvh[(size_t)(gr0 + 8) * 512 + koff]) = __floats2half2_rn(v10, v11);
                }
            }
        }
    }
}

// ---------------- fused attention + head mean + skip + tanh + MLP ----------------
// Warp per dst node. Lane l owns dims [8l, 8l+8) (head l/8).
// No max-subtraction (logits ~N(0,1); overflow impossible). Then fused 64x64 matvec.
__global__ void __launch_bounds__(256) attn_kernel(float* __restrict__ out, int n) {
    __shared__ float Wsm[64 * 66];
    __shared__ float hsm[8][64];
    int tid = threadIdx.x;
    int lane = tid & 31;
    int w = tid >> 5;

    // cooperative Wms load (64x64 -> padded 66)
    for (int i = tid; i < 4096; i += 256) Wsm[(i >> 6) * 66 + (i & 63)] = g_Wms[i];

    int gw = blockIdx.x * 8 + w;
    bool valid = gw < n;

    if (valid) {
        const float4* qp = reinterpret_cast<const float4*>(g_q + (size_t)gw * QKVDIM + lane * 8);
        float4 q0 = qp[0], q1 = qp[1];

        int start = g_rowstart[gw], end = g_rowstart[gw + 1];
        float S[8] = {0.f, 0.f, 0.f, 0.f, 0.f, 0.f, 0.f, 0.f};
        float d = 0.f;

        for (int p = start; p < end; ++p) {
            int src = g_esrc[p];
            const uint4* kv = reinterpret_cast<const uint4*>(g_kvh + (size_t)src * 512);
            uint4 kk = kv[lane];
            uint4 vv = kv[lane + 32];
            float2 k0 = __half22float2(*reinterpret_cast<__half2*>(&kk.x));
            float2 k1 = __half22float2(*reinterpret_cast<__half2*>(&kk.y));
            float2 k2 = __half22float2(*reinterpret_cast<__half2*>(&kk.z));
            float2 k3 = __half22float2(*reinterpret_cast<__half2*>(&kk.w));
            float t = q0.x * k0.x + q0.y * k0.y + q0.z * k1.x + q0.w * k1.y
                    + q1.x * k2.x + q1.y * k2.y + q1.z * k3.x + q1.w * k3.y;
            t += __shfl_xor_sync(0xFFFFFFFFu, t, 1);
            t += __shfl_xor_sync(0xFFFFFFFFu, t, 2);
            t += __shfl_xor_sync(0xFFFFFFFFu, t, 4);
            float e = __expf(t * 0.125f);
            d += e;
            float2 v0 = __half22float2(*reinterpret_cast<__half2*>(&vv.x));
            float2 v1 = __half22float2(*reinterpret_cast<__half2*>(&vv.y));
            float2 v2 = __half22float2(*reinterpret_cast<__half2*>(&vv.z));
            float2 v3 = __half22float2(*reinterpret_cast<__half2*>(&vv.w));
            S[0] += e * v0.x; S[1] += e * v0.y; S[2] += e * v1.x; S[3] += e * v1.y;
            S[4] += e * v2.x; S[5] += e * v2.y; S[6] += e * v3.x; S[7] += e * v3.y;
        }

        float r = 1.f / (d + 1e-16f);
#pragma unroll
        for (int j = 0; j < 8; ++j) {
            float s = S[j] * r;
            s += __shfl_xor_sync(0xFFFFFFFFu, s, 8);
            s += __shfl_xor_sync(0xFFFFFFFFu, s, 16);
            S[j] = s;  // now: sum over 4 heads for dim slot (lane&7)*8 + j
        }

        if (lane < 8) {
            const float* sk = g_skip + (size_t)gw * HID + lane * 8;
#pragma unroll
            for (int j = 0; j < 8; ++j)
                hsm[w][lane * 8 + j] = tanhf(0.25f * S[j] + sk[j]);
        }
    }
    __syncwarp();
    __syncthreads();  // Wsm ready (all warps reach here)

    if (valid) {
        const float* hrow = hsm[w];
        float acc0 = 0.f, acc1 = 0.f;
#pragma unroll 8
        for (int dd = 0; dd < 64; ++dd) {
            float hv = hrow[dd];
            float2 wv = *reinterpret_cast<const float2*>(&Wsm[dd * 66 + lane * 2]);
            acc0 += hv * wv.x;
            acc1 += hv * wv.y;
        }
        *reinterpret_cast<float2*>(out + (size_t)gw * OUTD + lane * 2) = make_float2(acc0, acc1);
    }
}

// ---------------- launch ----------------
extern "C" void kernel_launch(void* const* d_in, const int* in_sizes, int n_in,
                              void* d_out, int out_size) {
    const float* x     = (const float*)d_in[0];
    const int*   ei    = (const int*)  d_in[1];
    const float* Wq    = (const float*)d_in[2];
    const float* bq    = (const float*)d_in[3];
    const float* Wk    = (const float*)d_in[4];
    const float* bk    = (const float*)d_in[5];
    const float* Wv    = (const float*)d_in[6];
    const float* bv    = (const float*)d_in[7];
    const float* Wskip = (const float*)d_in[8];
    const float* bskip = (const float*)d_in[9];
    const float* Wmlp  = (const float*)d_in[10];
    float* out = (float*)d_out;

    int N = in_sizes[0] / INDIM;
    int E = in_sizes[1] / 2;

    cudaFuncSetAttribute(gemm_mma_kernel, cudaFuncAttributeMaxDynamicSharedMemorySize,
                         GEMM_SMEM_BYTES);

    // CSR build (independent of projections)
    zero_kernel<<<(N + 255) / 256, 256>>>(N);
    hist_kernel<<<(E + 255) / 256, 256>>>(ei, E);
    scan_kernel<<<1, 1024>>>(N);
    scatter_edges_kernel<<<(E + 255) / 256, 256>>>(ei, E);

    // projections
    prep_kernel<<<(COLS_ALL * INDIM + 255) / 256, 256>>>(Wq, bq, Wk, bk, Wv, bv, Wskip, bskip);
    sigma_kernel<<<1, 64>>>(Wmlp);
    int mblocks = (N + 127) / 128;
    gemm_mma_kernel<<<mblocks, 256, GEMM_SMEM_BYTES>>>(x, N);

    // fused attention + epilogue + MLP
    attn_kernel<<<(N + 7) / 8, 256>>>(out, N);
}

// round 6
// speedup vs baseline: 2.3690x; 1.1703x over previous
#include <cuda_runtime.h>
#include <cuda_fp16.h>
#include <math.h>
#include <stdint.h>

// Problem constants
#define NMAX 50000
#define EMAX 300000
#define INDIM 128
#define HID 64
#define HEADS 4
#define QKVDIM 256
#define COLS_ALL 832    // Wq|Wk|Wv|Wskip
#define OUTD 64
#define NTILES 13

// ---------------- scratch ----------------
__device__ float g_ball[COLS_ALL];
__device__ __align__(16) __half g_Wt_h[COLS_ALL * INDIM];
__device__ float g_q[(size_t)NMAX * QKVDIM];
__device__ __align__(16) __half g_kvh[(size_t)NMAX * 512];  // k[256] | v[256] fp16
__device__ float g_skip[(size_t)NMAX * HID];
__device__ float g_Wms[HID * OUTD];
__device__ int g_deg[NMAX];
__device__ int g_cursor[NMAX];
__device__ int g_rowstart[NMAX + 1];
__device__ int g_esrc[EMAX];

// ---------------- helpers ----------------
__device__ __forceinline__ uint32_t smem_u32(const void* p) {
    uint32_t a;
    asm("{ .reg .u64 t; cvta.to.shared.u64 t, %1; cvt.u32.u64 %0, t; }" : "=r"(a) : "l"(p));
    return a;
}

#define LDMX4(r0, r1, r2, r3, addr) \
    asm volatile("ldmatrix.sync.aligned.m8n8.x4.shared.b16 {%0,%1,%2,%3}, [%4];" \
                 : "=r"(r0), "=r"(r1), "=r"(r2), "=r"(r3) : "r"(addr))

#define MMA16816H(d, a, b0, b1) \
    asm volatile("mma.sync.aligned.m16n8k16.row.col.f32.f16.f16.f32 " \
                 "{%0,%1,%2,%3},{%4,%5,%6,%7},{%8,%9},{%0,%1,%2,%3};" \
                 : "+f"((d)[0]), "+f"((d)[1]), "+f"((d)[2]), "+f"((d)[3]) \
                 : "r"((a)[0]), "r"((a)[1]), "r"((a)[2]), "r"((a)[3]), "r"(b0), "r"(b1))

// ---------------- prep: pack weights fp16 transposed + biases ----------------
__global__ void prep_kernel(const float* __restrict__ Wq, const float* __restrict__ bq,
                            const float* __restrict__ Wk, const float* __restrict__ bk,
                            const float* __restrict__ Wv, const float* __restrict__ bv,
                            const float* __restrict__ Ws, const float* __restrict__ bs) {
    int i = blockIdx.x * blockDim.x + threadIdx.x;
    if (i < COLS_ALL) {
        float b = (i < 256) ? bq[i] : (i < 512) ? bk[i - 256] : (i < 768) ? bv[i - 512] : bs[i - 768];
        g_ball[i] = b;
    }
    if (i < COLS_ALL * INDIM) {
        int n = i / INDIM, k = i % INDIM;
        float w = (n < 256) ? Wq[k * 256 + n]
                : (n < 512) ? Wk[k * 256 + (n - 256)]
                : (n < 768) ? Wv[k * 256 + (n - 512)]
                :             Ws[k * 64  + (n - 768)];
        g_Wt_h[i] = __float2half_rn(w);
    }
}

// ---------------- spectral norm power iteration ----------------
__global__ void sigma_kernel(const float* __restrict__ Wmlp) {
    __shared__ float Wsh[64][65];
    __shared__ float u[64], vv[64], upre[64], red[64];
    int t = threadIdx.x;
    for (int i = 0; i < 64; ++i) Wsh[i][t] = Wmlp[i * 64 + t];
    u[t] = 0.125f;
    __syncthreads();
    for (int it = 0; it < 20; ++it) {
        float s = 0.f;
        for (int i = 0; i < 64; ++i) s += Wsh[i][t] * u[i];
        red[t] = s * s; __syncthreads();
        for (int off = 32; off > 0; off >>= 1) { if (t < off) red[t] += red[t + off]; __syncthreads(); }
        float nv = sqrtf(red[0]);
        vv[t] = s / (nv + 1e-12f);
        __syncthreads();
        float s2 = 0.f;
        for (int j = 0; j < 64; ++j) s2 += Wsh[t][j] * vv[j];
        upre[t] = s2;
        red[t] = s2 * s2; __syncthreads();
        for (int off = 32; off > 0; off >>= 1) { if (t < off) red[t] += red[t + off]; __syncthreads(); }
        float nu = sqrtf(red[0]);
        u[t] = s2 / (nu + 1e-12f);
        __syncthreads();
    }
    red[t] = u[t] * upre[t]; __syncthreads();
    for (int off = 32; off > 0; off >>= 1) { if (t < off) red[t] += red[t + off]; __syncthreads(); }
    float sigma = red[0];
    for (int j = 0; j < 64; ++j) g_Wms[t * 64 + j] = Wsh[t][j] / sigma;
}

// ---------------- CSR build ----------------
__global__ void zero_kernel(int n) {
    int i = blockIdx.x * blockDim.x + threadIdx.x;
    if (i < n) { g_deg[i] = 0; g_cursor[i] = 0; }
}
__global__ void hist_kernel(const int* __restrict__ ei, int E) {
    int e = blockIdx.x * blockDim.x + threadIdx.x;
    if (e < E) atomicAdd(&g_deg[ei[E + e]], 1);
}
__global__ void scan_kernel(int n) {
    __shared__ int s[1024];
    int t = threadIdx.x;
    int chunk = (n + 1023) >> 10;
    int lo = t * chunk, hi = min(lo + chunk, n);
    int sum = 0;
    for (int i = lo; i < hi; ++i) sum += g_deg[i];
    s[t] = sum; __syncthreads();
    for (int off = 1; off < 1024; off <<= 1) {
        int v = (t >= off) ? s[t - off] : 0;
        __syncthreads();
        if (t >= off) s[t] += v;
        __syncthreads();
    }
    int run = (t == 0) ? 0 : s[t - 1];
    for (int i = lo; i < hi; ++i) { g_rowstart[i] = run; run += g_deg[i]; }
    if (lo < n && hi == n) g_rowstart[n] = run;
}
__global__ void scatter_edges_kernel(const int* __restrict__ ei, int E) {
    int e = blockIdx.x * blockDim.x + threadIdx.x;
    if (e >= E) return;
    int dst = ei[E + e];
    int pos = g_rowstart[dst] + atomicAdd(&g_cursor[dst], 1);
    g_esrc[pos] = ei[e];
}

// ---------------- fp16 mma.sync projection GEMM: [N,128] x [128,832] ----------------
// q/skip tiles: 2-pass (Ahi*B + Alo*B). k/v tiles: single pass (they become fp16 anyway).
#define LDA_B 272
#define SM_A_HI 0
#define SM_A_LO 34816
#define SM_B 69632
#define GEMM_SMEM_BYTES 87040

__global__ void __launch_bounds__(256) gemm_mma_kernel(const float* __restrict__ x, int nrows) {
    extern __shared__ __align__(16) char sm[];
    const uint32_t s_base = smem_u32(sm);

    int tid = threadIdx.x;
    int lane = tid & 31;
    int wid = tid >> 5;
    int wm = wid & 3;
    int wn = wid >> 2;
    int row0 = blockIdx.x * 128;

    // ---- A fill: fp32 -> fp16 hi/lo ----
    {
#pragma unroll
        for (int p = 0; p < 16; ++p) {
            int idx = tid + p * 256;
            int row = idx >> 5;
            int c4 = idx & 31;
            int gr = row0 + row;
            float4 v = make_float4(0.f, 0.f, 0.f, 0.f);
            if (gr < nrows) v = *reinterpret_cast<const float4*>(x + (size_t)gr * INDIM + c4 * 4);
            __half h0 = __float2half_rn(v.x), h1 = __float2half_rn(v.y);
            __half h2 = __float2half_rn(v.z), h3 = __float2half_rn(v.w);
            __half l0 = __float2half_rn(v.x - __half2float(h0));
            __half l1 = __float2half_rn(v.y - __half2float(h1));
            __half l2 = __float2half_rn(v.z - __half2float(h2));
            __half l3 = __float2half_rn(v.w - __half2float(h3));
            uint32_t hp0 = ((uint32_t)*(unsigned short*)&h1 << 16) | *(unsigned short*)&h0;
            uint32_t hp1 = ((uint32_t)*(unsigned short*)&h3 << 16) | *(unsigned short*)&h2;
            uint32_t lp0 = ((uint32_t)*(unsigned short*)&l1 << 16) | *(unsigned short*)&l0;
            uint32_t lp1 = ((uint32_t)*(unsigned short*)&l3 << 16) | *(unsigned short*)&l2;
            uint32_t off = (uint32_t)row * LDA_B + (uint32_t)c4 * 8;
            *reinterpret_cast<uint2*>(sm + SM_A_HI + off) = make_uint2(hp0, hp1);
            *reinterpret_cast<uint2*>(sm + SM_A_LO + off) = make_uint2(lp0, lp1);
        }
    }

    int ar = lane & 15, ac8 = lane >> 4;
    int bg = lane >> 3;
    int bn = ((bg >> 1) << 3) + (lane & 7);
    int bk8 = bg & 1;
    uint32_t a_lane_off = (uint32_t)(wm * 32 + ar) * LDA_B + (uint32_t)ac8 * 16;
    uint32_t b_lane_off = (uint32_t)(wn * 32 + bn) * LDA_B + (uint32_t)bk8 * 16;

    for (int nb = 0; nb < NTILES; ++nb) {
        int col0 = nb * 64;
        int sel = nb >> 2;                       // 0=q 1=k 2=v 3=skip
        bool twopass = (sel == 0) || (sel == 3);
        __syncthreads();
#pragma unroll
        for (int p = 0; p < 4; ++p) {
            int idx = tid + p * 256;
            int row = idx >> 4;
            int c8 = idx & 15;
            size_t gb = ((size_t)(col0 + row) * INDIM + c8 * 8);
            uint4 vh = *reinterpret_cast<const uint4*>(&g_Wt_h[gb]);
            uint32_t off = (uint32_t)row * LDA_B + (uint32_t)c8 * 16;
            *reinterpret_cast<uint4*>(sm + SM_B + off) = vh;
        }
        __syncthreads();

        float acc[2][4][4];
#pragma unroll
        for (int mb = 0; mb < 2; ++mb)
#pragma unroll
            for (int jn = 0; jn < 4; ++jn)
#pragma unroll
                for (int r = 0; r < 4; ++r) acc[mb][jn][r] = 0.f;

#pragma unroll 2
        for (int kk = 0; kk < 8; ++kk) {
            uint32_t kbyte = (uint32_t)kk * 32;
            uint32_t ah[8], al[8], bb[8];
            uint32_t aaddr0 = s_base + SM_A_HI + a_lane_off + kbyte;
            LDMX4(ah[0], ah[1], ah[2], ah[3], aaddr0);
            LDMX4(ah[4], ah[5], ah[6], ah[7], aaddr0 + 16 * LDA_B);
            uint32_t baddr0 = s_base + SM_B + b_lane_off + kbyte;
            LDMX4(bb[0], bb[1], bb[2], bb[3], baddr0);
            LDMX4(bb[4], bb[5], bb[6], bb[7], baddr0 + 16 * LDA_B);
            if (twopass) {
                uint32_t aaddr1 = s_base + SM_A_LO + a_lane_off + kbyte;
                LDMX4(al[0], al[1], al[2], al[3], aaddr1);
                LDMX4(al[4], al[5], al[6], al[7], aaddr1 + 16 * LDA_B);
            }
#pragma unroll
            for (int mb = 0; mb < 2; ++mb) {
#pragma unroll
                for (int jn = 0; jn < 4; ++jn) {
                    MMA16816H(acc[mb][jn], &ah[mb * 4], bb[jn * 2], bb[jn * 2 + 1]);
                    if (twopass)
                        MMA16816H(acc[mb][jn], &al[mb * 4], bb[jn * 2], bb[jn * 2 + 1]);
                }
            }
        }

        int g = lane >> 2, t2 = (lane & 3) * 2;
#pragma unroll
        for (int mb = 0; mb < 2; ++mb) {
            int gr0 = row0 + wm * 32 + mb * 16 + g;
#pragma unroll
            for (int jn = 0; jn < 4; ++jn) {
                int gc = col0 + wn * 32 + jn * 8 + t2;
                float b0 = g_ball[gc], b1 = g_ball[gc + 1];
                float v00 = acc[mb][jn][0] + b0, v01 = acc[mb][jn][1] + b1;
                float v10 = acc[mb][jn][2] + b0, v11 = acc[mb][jn][3] + b1;
                if (sel == 0) {
                    if (gr0 < nrows)
                        *reinterpret_cast<float2*>(g_q + (size_t)gr0 * QKVDIM + gc) = make_float2(v00, v01);
                    if (gr0 + 8 < nrows)
                        *reinterpret_cast<float2*>(g_q + (size_t)(gr0 + 8) * QKVDIM + gc) = make_float2(v10, v11);
                } else if (sel == 3) {
                    int sc = gc - 768;
                    if (gr0 < nrows)
                        *reinterpret_cast<float2*>(g_skip + (size_t)gr0 * HID + sc) = make_float2(v00, v01);
                    if (gr0 + 8 < nrows)
                        *reinterpret_cast<float2*>(g_skip + (size_t)(gr0 + 8) * HID + sc) = make_float2(v10, v11);
                } else {
                    int koff = gc - 256;   // k: [0,256)  v: [256,512)
                    if (gr0 < nrows)
                        *reinterpret_cast<__half2*>(&g_kvh[(size_t)gr0 * 512 + koff]) = __floats2half2_rn(v00, v01);
                    if (gr0 + 8 < nrows)
                        *reinterpret_cast<__half2*>(&g_kvh[(size_t)(gr0 + 8) * 512 + koff]) = __floats2half2_rn(v10, v11);
                }
            }
        }
    }
}

// ---------------- fused attention + head mean + skip + tanh + MLP ----------------
// Warp per dst node, 2-edge unrolled online accumulation (no max-sub: logits ~N(0,1)).
__global__ void __launch_bounds__(256) attn_kernel(float* __restrict__ out, int n) {
    __shared__ float Wsm[64 * 66];
    __shared__ float hsm[8][64];
    int tid = threadIdx.x;
    int lane = tid & 31;
    int w = tid >> 5;

    for (int i = tid; i < 4096; i += 256) Wsm[(i >> 6) * 66 + (i & 63)] = g_Wms[i];

    int gw = blockIdx.x * 8 + w;
    bool valid = gw < n;

    if (valid) {
        const float4* qp = reinterpret_cast<const float4*>(g_q + (size_t)gw * QKVDIM + lane * 8);
        float4 q0 = qp[0], q1 = qp[1];

        int start = g_rowstart[gw], end = g_rowstart[gw + 1];
        float S[8] = {0.f, 0.f, 0.f, 0.f, 0.f, 0.f, 0.f, 0.f};
        float d = 0.f;

        int p = start;
        for (; p + 2 <= end; p += 2) {
            int s0 = g_esrc[p], s1 = g_esrc[p + 1];
            const uint4* kv0 = reinterpret_cast<const uint4*>(g_kvh + (size_t)s0 * 512);
            const uint4* kv1 = reinterpret_cast<const uint4*>(g_kvh + (size_t)s1 * 512);
            uint4 ka = kv0[lane], kb = kv1[lane];
            uint4 va = kv0[lane + 32], vb = kv1[lane + 32];
            float2 a0 = __half22float2(*reinterpret_cast<__half2*>(&ka.x));
            float2 a1 = __half22float2(*reinterpret_cast<__half2*>(&ka.y));
            float2 a2 = __half22float2(*reinterpret_cast<__half2*>(&ka.z));
            float2 a3 = __half22float2(*reinterpret_cast<__half2*>(&ka.w));
            float2 b0 = __half22float2(*reinterpret_cast<__half2*>(&kb.x));
            float2 b1 = __half22float2(*reinterpret_cast<__half2*>(&kb.y));
            float2 b2 = __half22float2(*reinterpret_cast<__half2*>(&kb.z));
            float2 b3 = __half22float2(*reinterpret_cast<__half2*>(&kb.w));
            float t0 = q0.x * a0.x + q0.y * a0.y + q0.z * a1.x + q0.w * a1.y
                     + q1.x * a2.x + q1.y * a2.y + q1.z * a3.x + q1.w * a3.y;
            float t1 = q0.x * b0.x + q0.y * b0.y + q0.z * b1.x + q0.w * b1.y
                     + q1.x * b2.x + q1.y * b2.y + q1.z * b3.x + q1.w * b3.y;
            t0 += __shfl_xor_sync(0xFFFFFFFFu, t0, 1);
            t1 += __shfl_xor_sync(0xFFFFFFFFu, t1, 1);
            t0 += __shfl_xor_sync(0xFFFFFFFFu, t0, 2);
            t1 += __shfl_xor_sync(0xFFFFFFFFu, t1, 2);
            t0 += __shfl_xor_sync(0xFFFFFFFFu, t0, 4);
            t1 += __shfl_xor_sync(0xFFFFFFFFu, t1, 4);
            float e0 = __expf(t0 * 0.125f);
            float e1 = __expf(t1 * 0.125f);
            d += e0 + e1;
            float2 w0 = __half22float2(*reinterpret_cast<__half2*>(&va.x));
            float2 w1 = __half22float2(*reinterpret_cast<__half2*>(&va.y));
            float2 w2 = __half22float2(*reinterpret_cast<__half2*>(&va.z));
            float2 w3 = __half22float2(*reinterpret_cast<__half2*>(&va.w));
            float2 u0 = __half22float2(*reinterpret_cast<__half2*>(&vb.x));
            float2 u1 = __half22float2(*reinterpret_cast<__half2*>(&vb.y));
            float2 u2 = __half22float2(*reinterpret_cast<__half2*>(&vb.z));
            float2 u3 = __half22float2(*reinterpret_cast<__half2*>(&vb.w));
            S[0] += e0 * w0.x + e1 * u0.x; S[1] += e0 * w0.y + e1 * u0.y;
            S[2] += e0 * w1.x + e1 * u1.x; S[3] += e0 * w1.y + e1 * u1.y;
            S[4] += e0 * w2.x + e1 * u2.x; S[5] += e0 * w2.y + e1 * u2.y;
            S[6] += e0 * w3.x + e1 * u3.x; S[7] += e0 * w3.y + e1 * u3.y;
        }
        if (p < end) {
            int s0 = g_esrc[p];
            const uint4* kv0 = reinterpret_cast<const uint4*>(g_kvh + (size_t)s0 * 512);
            uint4 ka = kv0[lane], va = kv0[lane + 32];
            float2 a0 = __half22float2(*reinterpret_cast<__half2*>(&ka.x));
            float2 a1 = __half22float2(*reinterpret_cast<__half2*>(&ka.y));
            float2 a2 = __half22float2(*reinterpret_cast<__half2*>(&ka.z));
            float2 a3 = __half22float2(*reinterpret_cast<__half2*>(&ka.w));
            float t0 = q0.x * a0.x + q0.y * a0.y + q0.z * a1.x + q0.w * a1.y
                     + q1.x * a2.x + q1.y * a2.y + q1.z * a3.x + q1.w * a3.y;
            t0 += __shfl_xor_sync(0xFFFFFFFFu, t0, 1);
            t0 += __shfl_xor_sync(0xFFFFFFFFu, t0, 2);
            t0 += __shfl_xor_sync(0xFFFFFFFFu, t0, 4);
            float e0 = __expf(t0 * 0.125f);
            d += e0;
            float2 w0 = __half22float2(*reinterpret_cast<__half2*>(&va.x));
            float2 w1 = __half22float2(*reinterpret_cast<__half2*>(&va.y));
            float2 w2 = __half22float2(*reinterpret_cast<__half2*>(&va.z));
            float2 w3 = __half22float2(*reinterpret_cast<__half2*>(&va.w));
            S[0] += e0 * w0.x; S[1] += e0 * w0.y;
            S[2] += e0 * w1.x; S[3] += e0 * w1.y;
            S[4] += e0 * w2.x; S[5] += e0 * w2.y;
            S[6] += e0 * w3.x; S[7] += e0 * w3.y;
        }

        float r = 1.f / (d + 1e-16f);
#pragma unroll
        for (int j = 0; j < 8; ++j) {
            float s = S[j] * r;
            s += __shfl_xor_sync(0xFFFFFFFFu, s, 8);
            s += __shfl_xor_sync(0xFFFFFFFFu, s, 16);
            S[j] = s;
        }

        if (lane < 8) {
            const float* sk = g_skip + (size_t)gw * HID + lane * 8;
#pragma unroll
            for (int j = 0; j < 8; ++j)
                hsm[w][lane * 8 + j] = tanhf(0.25f * S[j] + sk[j]);
        }
    }
    __syncwarp();
    __syncthreads();

    if (valid) {
        const float* hrow = hsm[w];
        float acc0 = 0.f, acc1 = 0.f;
#pragma unroll 8
        for (int dd = 0; dd < 64; ++dd) {
            float hv = hrow[dd];
            float2 wv = *reinterpret_cast<const float2*>(&Wsm[dd * 66 + lane * 2]);
            acc0 += hv * wv.x;
            acc1 += hv * wv.y;
        }
        *reinterpret_cast<float2*>(out + (size_t)gw * OUTD + lane * 2) = make_float2(acc0, acc1);
    }
}

// ---------------- launch ----------------
extern "C" void kernel_launch(void* const* d_in, const int* in_sizes, int n_in,
                              void* d_out, int out_size) {
    const float* x     = (const float*)d_in[0];
    const int*   ei    = (const int*)  d_in[1];
    const float* Wq    = (const float*)d_in[2];
    const float* bq    = (const float*)d_in[3];
    const float* Wk    = (const float*)d_in[4];
    const float* bk    = (const float*)d_in[5];
    const float* Wv    = (const float*)d_in[6];
    const float* bv    = (const float*)d_in[7];
    const float* Wskip = (const float*)d_in[8];
    const float* bskip = (const float*)d_in[9];
    const float* Wmlp  = (const float*)d_in[10];
    float* out = (float*)d_out;

    int N = in_sizes[0] / INDIM;
    int E = in_sizes[1] / 2;

    // one-time resources (created on the eager correctness call, reused during capture)
    static cudaStream_t s2 = nullptr;
    static cudaEvent_t evFork = nullptr, evJoin = nullptr;
    if (s2 == nullptr) {
        cudaStreamCreateWithFlags(&s2, cudaStreamNonBlocking);
        cudaEventCreateWithFlags(&evFork, cudaEventDisableTiming);
        cudaEventCreateWithFlags(&evJoin, cudaEventDisableTiming);
    }
    cudaFuncSetAttribute(gemm_mma_kernel, cudaFuncAttributeMaxDynamicSharedMemorySize,
                         GEMM_SMEM_BYTES);

    // fork: CSR chain on s2, projections on default stream
    cudaEventRecord(evFork, 0);
    cudaStreamWaitEvent(s2, evFork, 0);

    zero_kernel<<<(N + 255) / 256, 256, 0, s2>>>(N);
    hist_kernel<<<(E + 255) / 256, 256, 0, s2>>>(ei, E);
    scan_kernel<<<1, 1024, 0, s2>>>(N);
    scatter_edges_kernel<<<(E + 255) / 256, 256, 0, s2>>>(ei, E);
    cudaEventRecord(evJoin, s2);

    prep_kernel<<<(COLS_ALL * INDIM + 255) / 256, 256>>>(Wq, bq, Wk, bk, Wv, bv, Wskip, bskip);
    sigma_kernel<<<1, 64>>>(Wmlp);
    int mblocks = (N + 127) / 128;
    gemm_mma_kernel<<<mblocks, 256, GEMM_SMEM_BYTES>>>(x, N);

    // join, then fused attention + epilogue + MLP
    cudaStreamWaitEvent(0, evJoin, 0);
    attn_kernel<<<(N + 7) / 8, 256>>>(out, N);
}

// round 7
// speedup vs baseline: 2.3721x; 1.0013x over previous
#include <cuda_runtime.h>
#include <cuda_fp16.h>
#include <math.h>
#include <stdint.h>

// Problem constants
#define NMAX 50000
#define EMAX 300000
#define INDIM 128
#define HID 64
#define HEADS 4
#define QKVDIM 256
#define COLS_ALL 832    // Wq|Wk|Wv|Wskip
#define OUTD 64
#define NTILES 13

// ---------------- scratch ----------------
__device__ float g_ball[COLS_ALL];
__device__ __align__(16) __half g_Wt_h[COLS_ALL * INDIM];
__device__ float g_q[(size_t)NMAX * QKVDIM];
__device__ __align__(16) __half g_kvh[(size_t)NMAX * 512];  // k[256] | v[256] fp16
__device__ float g_skip[(size_t)NMAX * HID];
__device__ float g_Wms[HID * OUTD];
__device__ int g_deg[NMAX];
__device__ int g_cursor[NMAX];
__device__ int g_rowstart[NMAX + 1];
__device__ int g_esrc[EMAX];

// ---------------- helpers ----------------
__device__ __forceinline__ uint32_t smem_u32(const void* p) {
    uint32_t a;
    asm("{ .reg .u64 t; cvta.to.shared.u64 t, %1; cvt.u32.u64 %0, t; }" : "=r"(a) : "l"(p));
    return a;
}

#define LDMX4(r0, r1, r2, r3, addr) \
    asm volatile("ldmatrix.sync.aligned.m8n8.x4.shared.b16 {%0,%1,%2,%3}, [%4];" \
                 : "=r"(r0), "=r"(r1), "=r"(r2), "=r"(r3) : "r"(addr))

#define MMA16816H(d, a, b0, b1) \
    asm volatile("mma.sync.aligned.m16n8k16.row.col.f32.f16.f16.f32 " \
                 "{%0,%1,%2,%3},{%4,%5,%6,%7},{%8,%9},{%0,%1,%2,%3};" \
                 : "+f"((d)[0]), "+f"((d)[1]), "+f"((d)[2]), "+f"((d)[3]) \
                 : "r"((a)[0]), "r"((a)[1]), "r"((a)[2]), "r"((a)[3]), "r"(b0), "r"(b1))

// ---------------- prep: pack weights fp16 transposed + biases ----------------
__global__ void prep_kernel(const float* __restrict__ Wq, const float* __restrict__ bq,
                            const float* __restrict__ Wk, const float* __restrict__ bk,
                            const float* __restrict__ Wv, const float* __restrict__ bv,
                            const float* __restrict__ Ws, const float* __restrict__ bs) {
    int i = blockIdx.x * blockDim.x + threadIdx.x;
    if (i < COLS_ALL) {
        float b = (i < 256) ? bq[i] : (i < 512) ? bk[i - 256] : (i < 768) ? bv[i - 512] : bs[i - 768];
        g_ball[i] = b;
    }
    if (i < COLS_ALL * INDIM) {
        int n = i / INDIM, k = i % INDIM;
        float w = (n < 256) ? Wq[k * 256 + n]
                : (n < 512) ? Wk[k * 256 + (n - 256)]
                : (n < 768) ? Wv[k * 256 + (n - 512)]
                :             Ws[k * 64  + (n - 768)];
        g_Wt_h[i] = __float2half_rn(w);
    }
}

// ---------------- spectral norm power iteration ----------------
__global__ void sigma_kernel(const float* __restrict__ Wmlp) {
    __shared__ float Wsh[64][65];
    __shared__ float u[64], vv[64], upre[64], red[64];
    int t = threadIdx.x;
    for (int i = 0; i < 64; ++i) Wsh[i][t] = Wmlp[i * 64 + t];
    u[t] = 0.125f;
    __syncthreads();
    for (int it = 0; it < 20; ++it) {
        float s = 0.f;
        for (int i = 0; i < 64; ++i) s += Wsh[i][t] * u[i];
        red[t] = s * s; __syncthreads();
        for (int off = 32; off > 0; off >>= 1) { if (t < off) red[t] += red[t + off]; __syncthreads(); }
        float nv = sqrtf(red[0]);
        vv[t] = s / (nv + 1e-12f);
        __syncthreads();
        float s2 = 0.f;
        for (int j = 0; j < 64; ++j) s2 += Wsh[t][j] * vv[j];
        upre[t] = s2;
        red[t] = s2 * s2; __syncthreads();
        for (int off = 32; off > 0; off >>= 1) { if (t < off) red[t] += red[t + off]; __syncthreads(); }
        float nu = sqrtf(red[0]);
        u[t] = s2 / (nu + 1e-12f);
        __syncthreads();
    }
    red[t] = u[t] * upre[t]; __syncthreads();
    for (int off = 32; off > 0; off >>= 1) { if (t < off) red[t] += red[t + off]; __syncthreads(); }
    float sigma = red[0];
    for (int j = 0; j < 64; ++j) g_Wms[t * 64 + j] = Wsh[t][j] / sigma;
}

// ---------------- CSR build ----------------
__global__ void zero_kernel(int n) {
    int i = blockIdx.x * blockDim.x + threadIdx.x;
    if (i < n) { g_deg[i] = 0; g_cursor[i] = 0; }
}
__global__ void hist_kernel(const int* __restrict__ ei, int E) {
    int e = blockIdx.x * blockDim.x + threadIdx.x;
    if (e < E) atomicAdd(&g_deg[ei[E + e]], 1);
}
__global__ void scan_kernel(int n) {
    __shared__ int s[1024];
    int t = threadIdx.x;
    int chunk = (n + 1023) >> 10;
    int lo = t * chunk, hi = min(lo + chunk, n);
    int sum = 0;
    for (int i = lo; i < hi; ++i) sum += g_deg[i];
    s[t] = sum; __syncthreads();
    for (int off = 1; off < 1024; off <<= 1) {
        int v = (t >= off) ? s[t - off] : 0;
        __syncthreads();
        if (t >= off) s[t] += v;
        __syncthreads();
    }
    int run = (t == 0) ? 0 : s[t - 1];
    for (int i = lo; i < hi; ++i) { g_rowstart[i] = run; run += g_deg[i]; }
    if (lo < n && hi == n) g_rowstart[n] = run;
}
__global__ void scatter_edges_kernel(const int* __restrict__ ei, int E) {
    int e = blockIdx.x * blockDim.x + threadIdx.x;
    if (e >= E) return;
    int dst = ei[E + e];
    int pos = g_rowstart[dst] + atomicAdd(&g_cursor[dst], 1);
    g_esrc[pos] = ei[e];
}

// ---------------- fp16 mma.sync projection GEMM: [N,128] x [128,832] ----------------
// skip tiles: 2-pass (Ahi*B + Alo*B). q/k/v tiles: single pass fp16.
#define LDA_B 272
#define SM_A_HI 0
#define SM_A_LO 34816
#define SM_B 69632
#define GEMM_SMEM_BYTES 87040

__global__ void __launch_bounds__(256) gemm_mma_kernel(const float* __restrict__ x, int nrows) {
    extern __shared__ __align__(16) char sm[];
    const uint32_t s_base = smem_u32(sm);

    int tid = threadIdx.x;
    int lane = tid & 31;
    int wid = tid >> 5;
    int wm = wid & 3;
    int wn = wid >> 2;
    int row0 = blockIdx.x * 128;

    // ---- A fill: fp32 -> fp16 hi/lo ----
    {
#pragma unroll
        for (int p = 0; p < 16; ++p) {
            int idx = tid + p * 256;
            int row = idx >> 5;
            int c4 = idx & 31;
            int gr = row0 + row;
            float4 v = make_float4(0.f, 0.f, 0.f, 0.f);
            if (gr < nrows) v = *reinterpret_cast<const float4*>(x + (size_t)gr * INDIM + c4 * 4);
            __half h0 = __float2half_rn(v.x), h1 = __float2half_rn(v.y);
            __half h2 = __float2half_rn(v.z), h3 = __float2half_rn(v.w);
            __half l0 = __float2half_rn(v.x - __half2float(h0));
            __half l1 = __float2half_rn(v.y - __half2float(h1));
            __half l2 = __float2half_rn(v.z - __half2float(h2));
            __half l3 = __float2half_rn(v.w - __half2float(h3));
            uint32_t hp0 = ((uint32_t)*(unsigned short*)&h1 << 16) | *(unsigned short*)&h0;
            uint32_t hp1 = ((uint32_t)*(unsigned short*)&h3 << 16) | *(unsigned short*)&h2;
            uint32_t lp0 = ((uint32_t)*(unsigned short*)&l1 << 16) | *(unsigned short*)&l0;
            uint32_t lp1 = ((uint32_t)*(unsigned short*)&l3 << 16) | *(unsigned short*)&l2;
            uint32_t off = (uint32_t)row * LDA_B + (uint32_t)c4 * 8;
            *reinterpret_cast<uint2*>(sm + SM_A_HI + off) = make_uint2(hp0, hp1);
            *reinterpret_cast<uint2*>(sm + SM_A_LO + off) = make_uint2(lp0, lp1);
        }
    }

    int ar = lane & 15, ac8 = lane >> 4;
    int bg = lane >> 3;
    int bn = ((bg >> 1) << 3) + (lane & 7);
    int bk8 = bg & 1;
    uint32_t a_lane_off = (uint32_t)(wm * 32 + ar) * LDA_B + (uint32_t)ac8 * 16;
    uint32_t b_lane_off = (uint32_t)(wn * 32 + bn) * LDA_B + (uint32_t)bk8 * 16;

    for (int nb = 0; nb < NTILES; ++nb) {
        int col0 = nb * 64;
        int sel = nb >> 2;                       // 0=q 1=k 2=v 3=skip
        bool twopass = (sel == 3);
        __syncthreads();
#pragma unroll
        for (int p = 0; p < 4; ++p) {
            int idx = tid + p * 256;
            int row = idx >> 4;
            int c8 = idx & 15;
            size_t gb = ((size_t)(col0 + row) * INDIM + c8 * 8);
            uint4 vh = *reinterpret_cast<const uint4*>(&g_Wt_h[gb]);
            uint32_t off = (uint32_t)row * LDA_B + (uint32_t)c8 * 16;
            *reinterpret_cast<uint4*>(sm + SM_B + off) = vh;
        }
        __syncthreads();

        float acc[2][4][4];
#pragma unroll
        for (int mb = 0; mb < 2; ++mb)
#pragma unroll
            for (int jn = 0; jn < 4; ++jn)
#pragma unroll
                for (int r = 0; r < 4; ++r) acc[mb][jn][r] = 0.f;

#pragma unroll 2
        for (int kk = 0; kk < 8; ++kk) {
            uint32_t kbyte = (uint32_t)kk * 32;
            uint32_t ah[8], al[8], bb[8];
            uint32_t aaddr0 = s_base + SM_A_HI + a_lane_off + kbyte;
            LDMX4(ah[0], ah[1], ah[2], ah[3], aaddr0);
            LDMX4(ah[4], ah[5], ah[6], ah[7], aaddr0 + 16 * LDA_B);
            uint32_t baddr0 = s_base + SM_B + b_lane_off + kbyte;
            LDMX4(bb[0], bb[1], bb[2], bb[3], baddr0);
            LDMX4(bb[4], bb[5], bb[6], bb[7], baddr0 + 16 * LDA_B);
            if (twopass) {
                uint32_t aaddr1 = s_base + SM_A_LO + a_lane_off + kbyte;
                LDMX4(al[0], al[1], al[2], al[3], aaddr1);
                LDMX4(al[4], al[5], al[6], al[7], aaddr1 + 16 * LDA_B);
            }
#pragma unroll
            for (int mb = 0; mb < 2; ++mb) {
#pragma unroll
                for (int jn = 0; jn < 4; ++jn) {
                    MMA16816H(acc[mb][jn], &ah[mb * 4], bb[jn * 2], bb[jn * 2 + 1]);
                    if (twopass)
                        MMA16816H(acc[mb][jn], &al[mb * 4], bb[jn * 2], bb[jn * 2 + 1]);
                }
            }
        }

        int g = lane >> 2, t2 = (lane & 3) * 2;
#pragma unroll
        for (int mb = 0; mb < 2; ++mb) {
            int gr0 = row0 + wm * 32 + mb * 16 + g;
#pragma unroll
            for (int jn = 0; jn < 4; ++jn) {
                int gc = col0 + wn * 32 + jn * 8 + t2;
                float b0 = g_ball[gc], b1 = g_ball[gc + 1];
                float v00 = acc[mb][jn][0] + b0, v01 = acc[mb][jn][1] + b1;
                float v10 = acc[mb][jn][2] + b0, v11 = acc[mb][jn][3] + b1;
                if (sel == 0) {
                    if (gr0 < nrows)
                        *reinterpret_cast<float2*>(g_q + (size_t)gr0 * QKVDIM + gc) = make_float2(v00, v01);
                    if (gr0 + 8 < nrows)
                        *reinterpret_cast<float2*>(g_q + (size_t)(gr0 + 8) * QKVDIM + gc) = make_float2(v10, v11);
                } else if (sel == 3) {
                    int sc = gc - 768;
                    if (gr0 < nrows)
                        *reinterpret_cast<float2*>(g_skip + (size_t)gr0 * HID + sc) = make_float2(v00, v01);
                    if (gr0 + 8 < nrows)
                        *reinterpret_cast<float2*>(g_skip + (size_t)(gr0 + 8) * HID + sc) = make_float2(v10, v11);
                } else {
                    int koff = gc - 256;   // k: [0,256)  v: [256,512)
                    if (gr0 < nrows)
                        *reinterpret_cast<__half2*>(&g_kvh[(size_t)gr0 * 512 + koff]) = __floats2half2_rn(v00, v01);
                    if (gr0 + 8 < nrows)
                        *reinterpret_cast<__half2*>(&g_kvh[(size_t)(gr0 + 8) * 512 + koff]) = __floats2half2_rn(v10, v11);
                }
            }
        }
    }
}

// ---------------- fused attention + head mean + skip + tanh + MLP ----------------
// Warp per dst node, 4-edge unrolled accumulation (no max-sub: logits ~N(0,1)).
__global__ void __launch_bounds__(256) attn_kernel(float* __restrict__ out, int n) {
    __shared__ float Wsm[64 * 66];
    __shared__ float hsm[8][64];
    int tid = threadIdx.x;
    int lane = tid & 31;
    int w = tid >> 5;

    for (int i = tid; i < 4096; i += 256) Wsm[(i >> 6) * 66 + (i & 63)] = g_Wms[i];

    int gw = blockIdx.x * 8 + w;
    bool valid = gw < n;

    if (valid) {
        const float4* qp = reinterpret_cast<const float4*>(g_q + (size_t)gw * QKVDIM + lane * 8);
        float4 q0 = qp[0], q1 = qp[1];

        int start = g_rowstart[gw], end = g_rowstart[gw + 1];
        float S[8] = {0.f, 0.f, 0.f, 0.f, 0.f, 0.f, 0.f, 0.f};
        float d = 0.f;

        int p = start;
        for (; p + 4 <= end; p += 4) {
            uint4 kk[4], vv[4];
#pragma unroll
            for (int i = 0; i < 4; ++i) {
                int s = g_esrc[p + i];
                const uint4* kv = reinterpret_cast<const uint4*>(g_kvh + (size_t)s * 512);
                kk[i] = kv[lane];
                vv[i] = kv[lane + 32];
            }
            float t[4];
#pragma unroll
            for (int i = 0; i < 4; ++i) {
                float2 k0 = __half22float2(*reinterpret_cast<__half2*>(&kk[i].x));
                float2 k1 = __half22float2(*reinterpret_cast<__half2*>(&kk[i].y));
                float2 k2 = __half22float2(*reinterpret_cast<__half2*>(&kk[i].z));
                float2 k3 = __half22float2(*reinterpret_cast<__half2*>(&kk[i].w));
                t[i] = q0.x * k0.x + q0.y * k0.y + q0.z * k1.x + q0.w * k1.y
                     + q1.x * k2.x + q1.y * k2.y + q1.z * k3.x + q1.w * k3.y;
            }
#pragma unroll
            for (int i = 0; i < 4; ++i) t[i] += __shfl_xor_sync(0xFFFFFFFFu, t[i], 1);
#pragma unroll
            for (int i = 0; i < 4; ++i) t[i] += __shfl_xor_sync(0xFFFFFFFFu, t[i], 2);
#pragma unroll
            for (int i = 0; i < 4; ++i) t[i] += __shfl_xor_sync(0xFFFFFFFFu, t[i], 4);
            float e[4];
#pragma unroll
            for (int i = 0; i < 4; ++i) {
                e[i] = __expf(t[i] * 0.125f);
                d += e[i];
            }
#pragma unroll
            for (int i = 0; i < 4; ++i) {
                float2 v0 = __half22float2(*reinterpret_cast<__half2*>(&vv[i].x));
                float2 v1 = __half22float2(*reinterpret_cast<__half2*>(&vv[i].y));
                float2 v2 = __half22float2(*reinterpret_cast<__half2*>(&vv[i].z));
                float2 v3 = __half22float2(*reinterpret_cast<__half2*>(&vv[i].w));
                S[0] += e[i] * v0.x; S[1] += e[i] * v0.y;
                S[2] += e[i] * v1.x; S[3] += e[i] * v1.y;
                S[4] += e[i] * v2.x; S[5] += e[i] * v2.y;
                S[6] += e[i] * v3.x; S[7] += e[i] * v3.y;
            }
        }
        for (; p < end; ++p) {
            int s0 = g_esrc[p];
            const uint4* kv0 = reinterpret_cast<const uint4*>(g_kvh + (size_t)s0 * 512);
            uint4 ka = kv0[lane], va = kv0[lane + 32];
            float2 a0 = __half22float2(*reinterpret_cast<__half2*>(&ka.x));
            float2 a1 = __half22float2(*reinterpret_cast<__half2*>(&ka.y));
            float2 a2 = __half22float2(*reinterpret_cast<__half2*>(&ka.z));
            float2 a3 = __half22float2(*reinterpret_cast<__half2*>(&ka.w));
            float t0 = q0.x * a0.x + q0.y * a0.y + q0.z * a1.x + q0.w * a1.y
                     + q1.x * a2.x + q1.y * a2.y + q1.z * a3.x + q1.w * a3.y;
            t0 += __shfl_xor_sync(0xFFFFFFFFu, t0, 1);
            t0 += __shfl_xor_sync(0xFFFFFFFFu, t0, 2);
            t0 += __shfl_xor_sync(0xFFFFFFFFu, t0, 4);
            float e0 = __expf(t0 * 0.125f);
            d += e0;
            float2 w0 = __half22float2(*reinterpret_cast<__half2*>(&va.x));
            float2 w1 = __half22float2(*reinterpret_cast<__half2*>(&va.y));
            float2 w2 = __half22float2(*reinterpret_cast<__half2*>(&va.z));
            float2 w3 = __half22float2(*reinterpret_cast<__half2*>(&va.w));
            S[0] += e0 * w0.x; S[1] += e0 * w0.y;
            S[2] += e0 * w1.x; S[3] += e0 * w1.y;
            S[4] += e0 * w2.x; S[5] += e0 * w2.y;
            S[6] += e0 * w3.x; S[7] += e0 * w3.y;
        }

        float r = 1.f / (d + 1e-16f);
#pragma unroll
        for (int j = 0; j < 8; ++j) {
            float s = S[j] * r;
            s += __shfl_xor_sync(0xFFFFFFFFu, s, 8);
            s += __shfl_xor_sync(0xFFFFFFFFu, s, 16);
            S[j] = s;
        }

        if (lane < 8) {
            const float* sk = g_skip + (size_t)gw * HID + lane * 8;
#pragma unroll
            for (int j = 0; j < 8; ++j)
                hsm[w][lane * 8 + j] = tanhf(0.25f * S[j] + sk[j]);
        }
    }
    __syncwarp();
    __syncthreads();

    if (valid) {
        const float* hrow = hsm[w];
        float acc0 = 0.f, acc1 = 0.f;
#pragma unroll 8
        for (int dd = 0; dd < 64; ++dd) {
            float hv = hrow[dd];
            float2 wv = *reinterpret_cast<const float2*>(&Wsm[dd * 66 + lane * 2]);
            acc0 += hv * wv.x;
            acc1 += hv * wv.y;
        }
        *reinterpret_cast<float2*>(out + (size_t)gw * OUTD + lane * 2) = make_float2(acc0, acc1);
    }
}

// ---------------- launch ----------------
extern "C" void kernel_launch(void* const* d_in, const int* in_sizes, int n_in,
                              void* d_out, int out_size) {
    const float* x     = (const float*)d_in[0];
    const int*   ei    = (const int*)  d_in[1];
    const float* Wq    = (const float*)d_in[2];
    const float* bq    = (const float*)d_in[3];
    const float* Wk    = (const float*)d_in[4];
    const float* bk    = (const float*)d_in[5];
    const float* Wv    = (const float*)d_in[6];
    const float* bv    = (const float*)d_in[7];
    const float* Wskip = (const float*)d_in[8];
    const float* bskip = (const float*)d_in[9];
    const float* Wmlp  = (const float*)d_in[10];
    float* out = (float*)d_out;

    int N = in_sizes[0] / INDIM;
    int E = in_sizes[1] / 2;

    static cudaStream_t s2 = nullptr;
    static cudaEvent_t evFork = nullptr, evJoin = nullptr;
    if (s2 == nullptr) {
        cudaStreamCreateWithFlags(&s2, cudaStreamNonBlocking);
        cudaEventCreateWithFlags(&evFork, cudaEventDisableTiming);
        cudaEventCreateWithFlags(&evJoin, cudaEventDisableTiming);
    }
    cudaFuncSetAttribute(gemm_mma_kernel, cudaFuncAttributeMaxDynamicSharedMemorySize,
                         GEMM_SMEM_BYTES);

    // fork: CSR chain on s2, projections on default stream
    cudaEventRecord(evFork, 0);
    cudaStreamWaitEvent(s2, evFork, 0);

    zero_kernel<<<(N + 255) / 256, 256, 0, s2>>>(N);
    hist_kernel<<<(E + 255) / 256, 256, 0, s2>>>(ei, E);
    scan_kernel<<<1, 1024, 0, s2>>>(N);
    scatter_edges_kernel<<<(E + 255) / 256, 256, 0, s2>>>(ei, E);
    cudaEventRecord(evJoin, s2);

    prep_kernel<<<(COLS_ALL * INDIM + 255) / 256, 256>>>(Wq, bq, Wk, bk, Wv, bv, Wskip, bskip);
    sigma_kernel<<<1, 64>>>(Wmlp);
    int mblocks = (N + 127) / 128;
    gemm_mma_kernel<<<mblocks, 256, GEMM_SMEM_BYTES>>>(x, N);

    // join, then fused attention + epilogue + MLP
    cudaStreamWaitEvent(0, evJoin, 0);
    attn_kernel<<<(N + 7) / 8, 256>>>(out, N);
}

// round 8
// speedup vs baseline: 2.6509x; 1.1175x over previous
#include <cuda_runtime.h>
#include <cuda_fp16.h>
#include <math.h>
#include <stdint.h>

// Problem constants
#define NMAX 50000
#define EMAX 300000
#define INDIM 128
#define HID 64
#define HEADS 4
#define QKVDIM 256
#define COLS_ALL 832    // Wq|Wk|Wv|Wskip
#define OUTD 64
#define NTILES 13

// ---------------- scratch ----------------
__device__ float g_ball[COLS_ALL];
__device__ __align__(16) __half g_Wt_h[COLS_ALL * INDIM];
__device__ __align__(16) __half g_qh[(size_t)NMAX * QKVDIM];   // q fp16
__device__ __align__(16) __half g_kvh[(size_t)NMAX * 512];     // k[256] | v[256] fp16
__device__ float g_skip[(size_t)NMAX * HID];
__device__ float g_Wms[HID * OUTD];
__device__ int g_deg[NMAX];
__device__ int g_cursor[NMAX];
__device__ int g_rowstart[NMAX + 1];
__device__ int g_esrc[EMAX];

// ---------------- helpers ----------------
__device__ __forceinline__ uint32_t smem_u32(const void* p) {
    uint32_t a;
    asm("{ .reg .u64 t; cvta.to.shared.u64 t, %1; cvt.u32.u64 %0, t; }" : "=r"(a) : "l"(p));
    return a;
}

#define LDMX4(r0, r1, r2, r3, addr) \
    asm volatile("ldmatrix.sync.aligned.m8n8.x4.shared.b16 {%0,%1,%2,%3}, [%4];" \
                 : "=r"(r0), "=r"(r1), "=r"(r2), "=r"(r3) : "r"(addr))

#define MMA16816H(d, a, b0, b1) \
    asm volatile("mma.sync.aligned.m16n8k16.row.col.f32.f16.f16.f32 " \
                 "{%0,%1,%2,%3},{%4,%5,%6,%7},{%8,%9},{%0,%1,%2,%3};" \
                 : "+f"((d)[0]), "+f"((d)[1]), "+f"((d)[2]), "+f"((d)[3]) \
                 : "r"((a)[0]), "r"((a)[1]), "r"((a)[2]), "r"((a)[3]), "r"(b0), "r"(b1))

// ---------------- prep: pack weights fp16 transposed + biases ----------------
__global__ void prep_kernel(const float* __restrict__ Wq, const float* __restrict__ bq,
                            const float* __restrict__ Wk, const float* __restrict__ bk,
                            const float* __restrict__ Wv, const float* __restrict__ bv,
                            const float* __restrict__ Ws, const float* __restrict__ bs) {
    int i = blockIdx.x * blockDim.x + threadIdx.x;
    if (i < COLS_ALL) {
        float b = (i < 256) ? bq[i] : (i < 512) ? bk[i - 256] : (i < 768) ? bv[i - 512] : bs[i - 768];
        g_ball[i] = b;
    }
    if (i < COLS_ALL * INDIM) {
        int n = i / INDIM, k = i % INDIM;
        float w = (n < 256) ? Wq[k * 256 + n]
                : (n < 512) ? Wk[k * 256 + (n - 256)]
                : (n < 768) ? Wv[k * 256 + (n - 512)]
                :             Ws[k * 64  + (n - 768)];
        g_Wt_h[i] = __float2half_rn(w);
    }
}

// ---------------- spectral norm power iteration (warp-level, shfl reductions) ----------------
__global__ void sigma_kernel(const float* __restrict__ Wmlp) {
    __shared__ float Wsh[64 * 65];
    __shared__ float ush[64], vsh[64];
    int t = threadIdx.x;  // 32 threads
    for (int i = t; i < 4096; i += 32) {
        int r = i >> 6, c = i & 63;
        Wsh[r * 65 + c] = Wmlp[i];
    }
    ush[t] = 0.125f; ush[t + 32] = 0.125f;
    __syncwarp();
    float up0 = 0.f, up1 = 0.f;  // last pre-normalization u (thread rows t, t+32)
    for (int it = 0; it < 20; ++it) {
        // v = W^T u  (thread owns cols t, t+32)
        float s0 = 0.f, s1 = 0.f;
        for (int i = 0; i < 64; ++i) {
            float ui = ush[i];
            s0 += Wsh[i * 65 + t] * ui;
            s1 += Wsh[i * 65 + t + 32] * ui;
        }
        float nn = s0 * s0 + s1 * s1;
#pragma unroll
        for (int o = 16; o > 0; o >>= 1) nn += __shfl_xor_sync(0xFFFFFFFFu, nn, o);
        float inv = 1.f / (sqrtf(nn) + 1e-12f);
        vsh[t] = s0 * inv; vsh[t + 32] = s1 * inv;
        __syncwarp();
        // u = W v  (thread owns rows t, t+32)
        float r0 = 0.f, r1 = 0.f;
        for (int j = 0; j < 64; ++j) {
            float vj = vsh[j];
            r0 += Wsh[t * 65 + j] * vj;
            r1 += Wsh[(t + 32) * 65 + j] * vj;
        }
        up0 = r0; up1 = r1;
        float nu = r0 * r0 + r1 * r1;
#pragma unroll
        for (int o = 16; o > 0; o >>= 1) nu += __shfl_xor_sync(0xFFFFFFFFu, nu, o);
        float invu = 1.f / (sqrtf(nu) + 1e-12f);
        ush[t] = r0 * invu; ush[t + 32] = r1 * invu;
        __syncwarp();
    }
    float sg = ush[t] * up0 + ush[t + 32] * up1;
#pragma unroll
    for (int o = 16; o > 0; o >>= 1) sg += __shfl_xor_sync(0xFFFFFFFFu, sg, o);
    float rinv = 1.f / sg;
    for (int i = t; i < 4096; i += 32) {
        int r = i >> 6, c = i & 63;
        g_Wms[i] = Wsh[r * 65 + c] * rinv;
    }
}

// ---------------- CSR build ----------------
__global__ void zero_kernel(int n) {
    int i = blockIdx.x * blockDim.x + threadIdx.x;
    if (i < n) { g_deg[i] = 0; g_cursor[i] = 0; }
}
__global__ void hist_kernel(const int* __restrict__ ei, int E) {
    int e = blockIdx.x * blockDim.x + threadIdx.x;
    if (e < E) atomicAdd(&g_deg[ei[E + e]], 1);
}
__global__ void scan_kernel(int n) {
    __shared__ int s[1024];
    int t = threadIdx.x;
    int chunk = (n + 1023) >> 10;
    int lo = t * chunk, hi = min(lo + chunk, n);
    int sum = 0;
    for (int i = lo; i < hi; ++i) sum += g_deg[i];
    s[t] = sum; __syncthreads();
    for (int off = 1; off < 1024; off <<= 1) {
        int v = (t >= off) ? s[t - off] : 0;
        __syncthreads();
        if (t >= off) s[t] += v;
        __syncthreads();
    }
    int run = (t == 0) ? 0 : s[t - 1];
    for (int i = lo; i < hi; ++i) { g_rowstart[i] = run; run += g_deg[i]; }
    if (lo < n && hi == n) g_rowstart[n] = run;
}
__global__ void scatter_edges_kernel(const int* __restrict__ ei, int E) {
    int e = blockIdx.x * blockDim.x + threadIdx.x;
    if (e >= E) return;
    int dst = ei[E + e];
    int pos = g_rowstart[dst] + atomicAdd(&g_cursor[dst], 1);
    g_esrc[pos] = ei[e];
}

// ---------------- fp16 mma.sync projection GEMM: [N,128] x [128,832] ----------------
// skip tiles: 2-pass (Ahi*B + Alo*B). q/k/v tiles: single pass fp16.
// Grid: (mblocks, 2) — y=0 handles N-tiles 0..6, y=1 handles 7..12 (wave-tail smoothing).
#define LDA_B 272
#define SM_A_HI 0
#define SM_A_LO 34816
#define SM_B 69632
#define GEMM_SMEM_BYTES 87040

__global__ void __launch_bounds__(256) gemm_mma_kernel(const float* __restrict__ x, int nrows) {
    extern __shared__ __align__(16) char sm[];
    const uint32_t s_base = smem_u32(sm);

    int tid = threadIdx.x;
    int lane = tid & 31;
    int wid = tid >> 5;
    int wm = wid & 3;
    int wn = wid >> 2;
    int row0 = blockIdx.x * 128;
    int nb_lo = (blockIdx.y == 0) ? 0 : 7;
    int nb_hi = (blockIdx.y == 0) ? 7 : NTILES;

    // ---- A fill: fp32 -> fp16 hi/lo ----
    {
#pragma unroll
        for (int p = 0; p < 16; ++p) {
            int idx = tid + p * 256;
            int row = idx >> 5;
            int c4 = idx & 31;
            int gr = row0 + row;
            float4 v = make_float4(0.f, 0.f, 0.f, 0.f);
            if (gr < nrows) v = *reinterpret_cast<const float4*>(x + (size_t)gr * INDIM + c4 * 4);
            __half h0 = __float2half_rn(v.x), h1 = __float2half_rn(v.y);
            __half h2 = __float2half_rn(v.z), h3 = __float2half_rn(v.w);
            uint32_t hp0 = ((uint32_t)*(unsigned short*)&h1 << 16) | *(unsigned short*)&h0;
            uint32_t hp1 = ((uint32_t)*(unsigned short*)&h3 << 16) | *(unsigned short*)&h2;
            uint32_t off = (uint32_t)row * LDA_B + (uint32_t)c4 * 8;
            *reinterpret_cast<uint2*>(sm + SM_A_HI + off) = make_uint2(hp0, hp1);
            if (blockIdx.y == 1) {  // lo part only needed for skip tiles (nb 12)
                __half l0 = __float2half_rn(v.x - __half2float(h0));
                __half l1 = __float2half_rn(v.y - __half2float(h1));
                __half l2 = __float2half_rn(v.z - __half2float(h2));
                __half l3 = __float2half_rn(v.w - __half2float(h3));
                uint32_t lp0 = ((uint32_t)*(unsigned short*)&l1 << 16) | *(unsigned short*)&l0;
                uint32_t lp1 = ((uint32_t)*(unsigned short*)&l3 << 16) | *(unsigned short*)&l2;
                *reinterpret_cast<uint2*>(sm + SM_A_LO + off) = make_uint2(lp0, lp1);
            }
        }
    }

    int ar = lane & 15, ac8 = lane >> 4;
    int bg = lane >> 3;
    int bn = ((bg >> 1) << 3) + (lane & 7);
    int bk8 = bg & 1;
    uint32_t a_lane_off = (uint32_t)(wm * 32 + ar) * LDA_B + (uint32_t)ac8 * 16;
    uint32_t b_lane_off = (uint32_t)(wn * 32 + bn) * LDA_B + (uint32_t)bk8 * 16;

    for (int nb = nb_lo; nb < nb_hi; ++nb) {
        int col0 = nb * 64;
        int sel = nb >> 2;                       // 0=q 1=k 2=v 3=skip
        bool twopass = (sel == 3);
        __syncthreads();
#pragma unroll
        for (int p = 0; p < 4; ++p) {
            int idx = tid + p * 256;
            int row = idx >> 4;
            int c8 = idx & 15;
            size_t gb = ((size_t)(col0 + row) * INDIM + c8 * 8);
            uint4 vh = *reinterpret_cast<const uint4*>(&g_Wt_h[gb]);
            uint32_t off = (uint32_t)row * LDA_B + (uint32_t)c8 * 16;
            *reinterpret_cast<uint4*>(sm + SM_B + off) = vh;
        }
        __syncthreads();

        float acc[2][4][4];
#pragma unroll
        for (int mb = 0; mb < 2; ++mb)
#pragma unroll
            for (int jn = 0; jn < 4; ++jn)
#pragma unroll
                for (int r = 0; r < 4; ++r) acc[mb][jn][r] = 0.f;

#pragma unroll 2
        for (int kk = 0; kk < 8; ++kk) {
            uint32_t kbyte = (uint32_t)kk * 32;
            uint32_t ah[8], al[8], bb[8];
            uint32_t aaddr0 = s_base + SM_A_HI + a_lane_off + kbyte;
            LDMX4(ah[0], ah[1], ah[2], ah[3], aaddr0);
            LDMX4(ah[4], ah[5], ah[6], ah[7], aaddr0 + 16 * LDA_B);
            uint32_t baddr0 = s_base + SM_B + b_lane_off + kbyte;
            LDMX4(bb[0], bb[1], bb[2], bb[3], baddr0);
            LDMX4(bb[4], bb[5], bb[6], bb[7], baddr0 + 16 * LDA_B);
            if (twopass) {
                uint32_t aaddr1 = s_base + SM_A_LO + a_lane_off + kbyte;
                LDMX4(al[0], al[1], al[2], al[3], aaddr1);
                LDMX4(al[4], al[5], al[6], al[7], aaddr1 + 16 * LDA_B);
            }
#pragma unroll
            for (int mb = 0; mb < 2; ++mb) {
#pragma unroll
                for (int jn = 0; jn < 4; ++jn) {
                    MMA16816H(acc[mb][jn], &ah[mb * 4], bb[jn * 2], bb[jn * 2 + 1]);
                    if (twopass)
                        MMA16816H(acc[mb][jn], &al[mb * 4], bb[jn * 2], bb[jn * 2 + 1]);
                }
            }
        }

        int g = lane >> 2, t2 = (lane & 3) * 2;
#pragma unroll
        for (int mb = 0; mb < 2; ++mb) {
            int gr0 = row0 + wm * 32 + mb * 16 + g;
#pragma unroll
            for (int jn = 0; jn < 4; ++jn) {
                int gc = col0 + wn * 32 + jn * 8 + t2;
                float b0 = g_ball[gc], b1 = g_ball[gc + 1];
                float v00 = acc[mb][jn][0] + b0, v01 = acc[mb][jn][1] + b1;
                float v10 = acc[mb][jn][2] + b0, v11 = acc[mb][jn][3] + b1;
                if (sel == 0) {
                    if (gr0 < nrows)
                        *reinterpret_cast<__half2*>(&g_qh[(size_t)gr0 * QKVDIM + gc]) = __floats2half2_rn(v00, v01);
                    if (gr0 + 8 < nrows)
                        *reinterpret_cast<__half2*>(&g_qh[(size_t)(gr0 + 8) * QKVDIM + gc]) = __floats2half2_rn(v10, v11);
                } else if (sel == 3) {
                    int sc = gc - 768;
                    if (gr0 < nrows)
                        *reinterpret_cast<float2*>(g_skip + (size_t)gr0 * HID + sc) = make_float2(v00, v01);
                    if (gr0 + 8 < nrows)
                        *reinterpret_cast<float2*>(g_skip + (size_t)(gr0 + 8) * HID + sc) = make_float2(v10, v11);
                } else {
                    int koff = gc - 256;   // k: [0,256)  v: [256,512)
                    if (gr0 < nrows)
                        *reinterpret_cast<__half2*>(&g_kvh[(size_t)gr0 * 512 + koff]) = __floats2half2_rn(v00, v01);
                    if (gr0 + 8 < nrows)
                        *reinterpret_cast<__half2*>(&g_kvh[(size_t)(gr0 + 8) * 512 + koff]) = __floats2half2_rn(v10, v11);
                }
            }
        }
    }
}

// ---------------- fused attention + head mean + skip + tanh + MLP ----------------
// Warp per dst node; predicated 4-edge batches (deg 6 -> 2 dependent phases).
__global__ void __launch_bounds__(256) attn_kernel(float* __restrict__ out, int n) {
    __shared__ float Wsm[64 * 66];
    __shared__ float hsm[8][64];
    int tid = threadIdx.x;
    int lane = tid & 31;
    int w = tid >> 5;

    for (int i = tid; i < 4096; i += 256) Wsm[(i >> 6) * 66 + (i & 63)] = g_Wms[i];

    int gw = blockIdx.x * 8 + w;
    bool valid = gw < n;

    if (valid) {
        uint4 qv = *reinterpret_cast<const uint4*>(g_qh + (size_t)gw * QKVDIM + lane * 8);
        float2 q0 = __half22float2(*reinterpret_cast<__half2*>(&qv.x));
        float2 q1 = __half22float2(*reinterpret_cast<__half2*>(&qv.y));
        float2 q2 = __half22float2(*reinterpret_cast<__half2*>(&qv.z));
        float2 q3 = __half22float2(*reinterpret_cast<__half2*>(&qv.w));

        int start = g_rowstart[gw], end = g_rowstart[gw + 1];
        float S[8] = {0.f, 0.f, 0.f, 0.f, 0.f, 0.f, 0.f, 0.f};
        float d = 0.f;

        for (int p = start; p < end; p += 4) {
            int rem = end - p;  // >= 1
            int idx[4];
#pragma unroll
            for (int i = 0; i < 4; ++i) idx[i] = g_esrc[(i < rem) ? (p + i) : p];
            uint4 kk[4], vv[4];
#pragma unroll
            for (int i = 0; i < 4; ++i) {
                const uint4* kv = reinterpret_cast<const uint4*>(g_kvh + (size_t)idx[i] * 512);
                kk[i] = kv[lane];
                vv[i] = kv[lane + 32];
            }
            float t[4];
#pragma unroll
            for (int i = 0; i < 4; ++i) {
                float2 k0 = __half22float2(*reinterpret_cast<__half2*>(&kk[i].x));
                float2 k1 = __half22float2(*reinterpret_cast<__half2*>(&kk[i].y));
                float2 k2 = __half22float2(*reinterpret_cast<__half2*>(&kk[i].z));
                float2 k3 = __half22float2(*reinterpret_cast<__half2*>(&kk[i].w));
                t[i] = q0.x * k0.x + q0.y * k0.y + q1.x * k1.x + q1.y * k1.y
                     + q2.x * k2.x + q2.y * k2.y + q3.x * k3.x + q3.y * k3.y;
            }
#pragma unroll
            for (int i = 0; i < 4; ++i) t[i] += __shfl_xor_sync(0xFFFFFFFFu, t[i], 1);
#pragma unroll
            for (int i = 0; i < 4; ++i) t[i] += __shfl_xor_sync(0xFFFFFFFFu, t[i], 2);
#pragma unroll
            for (int i = 0; i < 4; ++i) t[i] += __shfl_xor_sync(0xFFFFFFFFu, t[i], 4);
            float e[4];
#pragma unroll
            for (int i = 0; i < 4; ++i) {
                e[i] = (i < rem) ? __expf(t[i] * 0.125f) : 0.f;
                d += e[i];
            }
#pragma unroll
            for (int i = 0; i < 4; ++i) {
                float2 v0 = __half22float2(*reinterpret_cast<__half2*>(&vv[i].x));
                float2 v1 = __half22float2(*reinterpret_cast<__half2*>(&vv[i].y));
                float2 v2 = __half22float2(*reinterpret_cast<__half2*>(&vv[i].z));
                float2 v3 = __half22float2(*reinterpret_cast<__half2*>(&vv[i].w));
                S[0] += e[i] * v0.x; S[1] += e[i] * v0.y;
                S[2] += e[i] * v1.x; S[3] += e[i] * v1.y;
                S[4] += e[i] * v2.x; S[5] += e[i] * v2.y;
                S[6] += e[i] * v3.x; S[7] += e[i] * v3.y;
            }
        }

        float r = 1.f / (d + 1e-16f);
#pragma unroll
        for (int j = 0; j < 8; ++j) {
            float s = S[j] * r;
            s += __shfl_xor_sync(0xFFFFFFFFu, s, 8);
            s += __shfl_xor_sync(0xFFFFFFFFu, s, 16);
            S[j] = s;
        }

        if (lane < 8) {
            const float* sk = g_skip + (size_t)gw * HID + lane * 8;
#pragma unroll
            for (int j = 0; j < 8; ++j)
                hsm[w][lane * 8 + j] = tanhf(0.25f * S[j] + sk[j]);
        }
    }
    __syncwarp();
    __syncthreads();

    if (valid) {
        const float* hrow = hsm[w];
        float acc0 = 0.f, acc1 = 0.f;
#pragma unroll 8
        for (int dd = 0; dd < 64; ++dd) {
            float hv = hrow[dd];
            float2 wv = *reinterpret_cast<const float2*>(&Wsm[dd * 66 + lane * 2]);
            acc0 += hv * wv.x;
            acc1 += hv * wv.y;
        }
        *reinterpret_cast<float2*>(out + (size_t)gw * OUTD + lane * 2) = make_float2(acc0, acc1);
    }
}

// ---------------- launch ----------------
extern "C" void kernel_launch(void* const* d_in, const int* in_sizes, int n_in,
                              void* d_out, int out_size) {
    const float* x     = (const float*)d_in[0];
    const int*   ei    = (const int*)  d_in[1];
    const float* Wq    = (const float*)d_in[2];
    const float* bq    = (const float*)d_in[3];
    const float* Wk    = (const float*)d_in[4];
    const float* bk    = (const float*)d_in[5];
    const float* Wv    = (const float*)d_in[6];
    const float* bv    = (const float*)d_in[7];
    const float* Wskip = (const float*)d_in[8];
    const float* bskip = (const float*)d_in[9];
    const float* Wmlp  = (const float*)d_in[10];
    float* out = (float*)d_out;

    int N = in_sizes[0] / INDIM;
    int E = in_sizes[1] / 2;

    static cudaStream_t s2 = nullptr;
    static cudaEvent_t evFork = nullptr, evJoin = nullptr;
    if (s2 == nullptr) {
        cudaStreamCreateWithFlags(&s2, cudaStreamNonBlocking);
        cudaEventCreateWithFlags(&evFork, cudaEventDisableTiming);
        cudaEventCreateWithFlags(&evJoin, cudaEventDisableTiming);
    }
    cudaFuncSetAttribute(gemm_mma_kernel, cudaFuncAttributeMaxDynamicSharedMemorySize,
                         GEMM_SMEM_BYTES);

    // fork: CSR chain + sigma on s2; projections on default stream
    cudaEventRecord(evFork, 0);
    cudaStreamWaitEvent(s2, evFork, 0);

    zero_kernel<<<(N + 255) / 256, 256, 0, s2>>>(N);
    hist_kernel<<<(E + 255) / 256, 256, 0, s2>>>(ei, E);
    scan_kernel<<<1, 1024, 0, s2>>>(N);
    scatter_edges_kernel<<<(E + 255) / 256, 256, 0, s2>>>(ei, E);
    sigma_kernel<<<1, 32, 0, s2>>>(Wmlp);
    cudaEventRecord(evJoin, s2);

    prep_kernel<<<(COLS_ALL * INDIM + 255) / 256, 256>>>(Wq, bq, Wk, bk, Wv, bv, Wskip, bskip);
    int mblocks = (N + 127) / 128;
    dim3 ggrid(mblocks, 2);
    gemm_mma_kernel<<<ggrid, 256, GEMM_SMEM_BYTES>>>(x, N);

    // join, then fused attention + epilogue + MLP
    cudaStreamWaitEvent(0, evJoin, 0);
    attn_kernel<<<(N + 7) / 8, 256>>>(out, N);
}

// round 9
// speedup vs baseline: 2.8959x; 1.0924x over previous
#include <cuda_runtime.h>
#include <cuda_fp16.h>
#include <math.h>
#include <stdint.h>

// Problem constants
#define NMAX 50000
#define EMAX 300000
#define INDIM 128
#define HID 64
#define HEADS 4
#define QKVDIM 256
#define COLS_ALL 832    // Wq|Wk|Wv|Wskip
#define OUTD 64
#define NTILES 13

// ---------------- scratch ----------------
__device__ float g_ball[COLS_ALL];
__device__ __align__(16) __half g_Wt_h[COLS_ALL * INDIM];
__device__ __align__(16) __half g_qh[(size_t)NMAX * QKVDIM];   // q fp16
__device__ __align__(16) __half g_kvh[(size_t)NMAX * 512];     // k[256] | v[256] fp16
__device__ float g_skip[(size_t)NMAX * HID];
__device__ float g_Wms[HID * OUTD];
__device__ int g_deg[NMAX];
__device__ int g_cursor[NMAX];
__device__ int g_rowstart[NMAX + 1];
__device__ int g_esrc[EMAX];

// ---------------- helpers ----------------
__device__ __forceinline__ uint32_t smem_u32(const void* p) {
    uint32_t a;
    asm("{ .reg .u64 t; cvta.to.shared.u64 t, %1; cvt.u32.u64 %0, t; }" : "=r"(a) : "l"(p));
    return a;
}

#define LDMX4(r0, r1, r2, r3, addr) \
    asm volatile("ldmatrix.sync.aligned.m8n8.x4.shared.b16 {%0,%1,%2,%3}, [%4];" \
                 : "=r"(r0), "=r"(r1), "=r"(r2), "=r"(r3) : "r"(addr))

#define MMA16816H(d, a, b0, b1) \
    asm volatile("mma.sync.aligned.m16n8k16.row.col.f32.f16.f16.f32 " \
                 "{%0,%1,%2,%3},{%4,%5,%6,%7},{%8,%9},{%0,%1,%2,%3};" \
                 : "+f"((d)[0]), "+f"((d)[1]), "+f"((d)[2]), "+f"((d)[3]) \
                 : "r"((a)[0]), "r"((a)[1]), "r"((a)[2]), "r"((a)[3]), "r"(b0), "r"(b1))

// ---------------- prep: pack weights fp16 transposed + biases ----------------
__global__ void prep_kernel(const float* __restrict__ Wq, const float* __restrict__ bq,
                            const float* __restrict__ Wk, const float* __restrict__ bk,
                            const float* __restrict__ Wv, const float* __restrict__ bv,
                            const float* __restrict__ Ws, const float* __restrict__ bs) {
    int i = blockIdx.x * blockDim.x + threadIdx.x;
    if (i < COLS_ALL) {
        float b = (i < 256) ? bq[i] : (i < 512) ? bk[i - 256] : (i < 768) ? bv[i - 512] : bs[i - 768];
        g_ball[i] = b;
    }
    if (i < COLS_ALL * INDIM) {
        int n = i / INDIM, k = i % INDIM;
        float w = (n < 256) ? Wq[k * 256 + n]
                : (n < 512) ? Wk[k * 256 + (n - 256)]
                : (n < 768) ? Wv[k * 256 + (n - 512)]
                :             Ws[k * 64  + (n - 768)];
        g_Wt_h[i] = __float2half_rn(w);
    }
}

// ---------------- spectral norm power iteration (warp-level) ----------------
__global__ void sigma_kernel(const float* __restrict__ Wmlp) {
    __shared__ float Wsh[64 * 65];
    __shared__ float ush[64], vsh[64];
    int t = threadIdx.x;  // 32 threads
    for (int i = t; i < 4096; i += 32) {
        int r = i >> 6, c = i & 63;
        Wsh[r * 65 + c] = Wmlp[i];
    }
    ush[t] = 0.125f; ush[t + 32] = 0.125f;
    __syncwarp();
    float up0 = 0.f, up1 = 0.f;
    for (int it = 0; it < 20; ++it) {
        float s0 = 0.f, s1 = 0.f;
        for (int i = 0; i < 64; ++i) {
            float ui = ush[i];
            s0 += Wsh[i * 65 + t] * ui;
            s1 += Wsh[i * 65 + t + 32] * ui;
        }
        float nn = s0 * s0 + s1 * s1;
#pragma unroll
        for (int o = 16; o > 0; o >>= 1) nn += __shfl_xor_sync(0xFFFFFFFFu, nn, o);
        float inv = 1.f / (sqrtf(nn) + 1e-12f);
        vsh[t] = s0 * inv; vsh[t + 32] = s1 * inv;
        __syncwarp();
        float r0 = 0.f, r1 = 0.f;
        for (int j = 0; j < 64; ++j) {
            float vj = vsh[j];
            r0 += Wsh[t * 65 + j] * vj;
            r1 += Wsh[(t + 32) * 65 + j] * vj;
        }
        up0 = r0; up1 = r1;
        float nu = r0 * r0 + r1 * r1;
#pragma unroll
        for (int o = 16; o > 0; o >>= 1) nu += __shfl_xor_sync(0xFFFFFFFFu, nu, o);
        float invu = 1.f / (sqrtf(nu) + 1e-12f);
        ush[t] = r0 * invu; ush[t + 32] = r1 * invu;
        __syncwarp();
    }
    float sg = ush[t] * up0 + ush[t + 32] * up1;
#pragma unroll
    for (int o = 16; o > 0; o >>= 1) sg += __shfl_xor_sync(0xFFFFFFFFu, sg, o);
    float rinv = 1.f / sg;
    for (int i = t; i < 4096; i += 32) {
        int r = i >> 6, c = i & 63;
        g_Wms[i] = Wsh[r * 65 + c] * rinv;
    }
}

// ---------------- CSR build ----------------
__global__ void zero_kernel(int n) {
    int i = blockIdx.x * blockDim.x + threadIdx.x;
    if (i < n) { g_deg[i] = 0; g_cursor[i] = 0; }
}
__global__ void hist_kernel(const int* __restrict__ ei, int E) {
    int e = blockIdx.x * blockDim.x + threadIdx.x;
    if (e < E) atomicAdd(&g_deg[ei[E + e]], 1);
}
__global__ void scan_kernel(int n) {
    __shared__ int s[1024];
    int t = threadIdx.x;
    int chunk = (n + 1023) >> 10;
    int lo = t * chunk, hi = min(lo + chunk, n);
    int sum = 0;
    for (int i = lo; i < hi; ++i) sum += g_deg[i];
    s[t] = sum; __syncthreads();
    for (int off = 1; off < 1024; off <<= 1) {
        int v = (t >= off) ? s[t - off] : 0;
        __syncthreads();
        if (t >= off) s[t] += v;
        __syncthreads();
    }
    int run = (t == 0) ? 0 : s[t - 1];
    for (int i = lo; i < hi; ++i) { g_rowstart[i] = run; run += g_deg[i]; }
    if (lo < n && hi == n) g_rowstart[n] = run;
}
__global__ void scatter_edges_kernel(const int* __restrict__ ei, int E) {
    int e = blockIdx.x * blockDim.x + threadIdx.x;
    if (e >= E) return;
    int dst = ei[E + e];
    int pos = g_rowstart[dst] + atomicAdd(&g_cursor[dst], 1);
    g_esrc[pos] = ei[e];
}

// ---------------- fp16 single-pass mma.sync projection GEMM ----------------
// smem: A (128x128 fp16, padded) + B (64x128 fp16) = 51 KB -> 4 CTAs/SM.
#define LDA_B 272
#define SM_A 0
#define SM_B 34816
#define GEMM_SMEM_BYTES 52224

__global__ void __launch_bounds__(256, 4) gemm_mma_kernel(const float* __restrict__ x, int nrows) {
    extern __shared__ __align__(16) char sm[];
    const uint32_t s_base = smem_u32(sm);

    int tid = threadIdx.x;
    int lane = tid & 31;
    int wid = tid >> 5;
    int wm = wid & 3;
    int wn = wid >> 2;
    int row0 = blockIdx.x * 128;
    int nb_lo = (blockIdx.y == 0) ? 0 : 7;
    int nb_hi = (blockIdx.y == 0) ? 7 : NTILES;

    // ---- A fill: fp32 -> fp16 ----
    {
#pragma unroll
        for (int p = 0; p < 16; ++p) {
            int idx = tid + p * 256;
            int row = idx >> 5;
            int c4 = idx & 31;
            int gr = row0 + row;
            float4 v = make_float4(0.f, 0.f, 0.f, 0.f);
            if (gr < nrows) v = *reinterpret_cast<const float4*>(x + (size_t)gr * INDIM + c4 * 4);
            __half h0 = __float2half_rn(v.x), h1 = __float2half_rn(v.y);
            __half h2 = __float2half_rn(v.z), h3 = __float2half_rn(v.w);
            uint32_t hp0 = ((uint32_t)*(unsigned short*)&h1 << 16) | *(unsigned short*)&h0;
            uint32_t hp1 = ((uint32_t)*(unsigned short*)&h3 << 16) | *(unsigned short*)&h2;
            uint32_t off = (uint32_t)row * LDA_B + (uint32_t)c4 * 8;
            *reinterpret_cast<uint2*>(sm + SM_A + off) = make_uint2(hp0, hp1);
        }
    }

    int ar = lane & 15, ac8 = lane >> 4;
    int bg = lane >> 3;
    int bn = ((bg >> 1) << 3) + (lane & 7);
    int bk8 = bg & 1;
    uint32_t a_lane_off = (uint32_t)(wm * 32 + ar) * LDA_B + (uint32_t)ac8 * 16;
    uint32_t b_lane_off = (uint32_t)(wn * 32 + bn) * LDA_B + (uint32_t)bk8 * 16;

    for (int nb = nb_lo; nb < nb_hi; ++nb) {
        int col0 = nb * 64;
        int sel = nb >> 2;                       // 0=q 1=k 2=v 3=skip
        __syncthreads();
#pragma unroll
        for (int p = 0; p < 4; ++p) {
            int idx = tid + p * 256;
            int row = idx >> 4;
            int c8 = idx & 15;
            size_t gb = ((size_t)(col0 + row) * INDIM + c8 * 8);
            uint4 vh = *reinterpret_cast<const uint4*>(&g_Wt_h[gb]);
            uint32_t off = (uint32_t)row * LDA_B + (uint32_t)c8 * 16;
            *reinterpret_cast<uint4*>(sm + SM_B + off) = vh;
        }
        __syncthreads();

        float acc[2][4][4];
#pragma unroll
        for (int mb = 0; mb < 2; ++mb)
#pragma unroll
            for (int jn = 0; jn < 4; ++jn)
#pragma unroll
                for (int r = 0; r < 4; ++r) acc[mb][jn][r] = 0.f;

#pragma unroll 2
        for (int kk = 0; kk < 8; ++kk) {
            uint32_t kbyte = (uint32_t)kk * 32;
            uint32_t ah[8], bb[8];
            uint32_t aaddr0 = s_base + SM_A + a_lane_off + kbyte;
            LDMX4(ah[0], ah[1], ah[2], ah[3], aaddr0);
            LDMX4(ah[4], ah[5], ah[6], ah[7], aaddr0 + 16 * LDA_B);
            uint32_t baddr0 = s_base + SM_B + b_lane_off + kbyte;
            LDMX4(bb[0], bb[1], bb[2], bb[3], baddr0);
            LDMX4(bb[4], bb[5], bb[6], bb[7], baddr0 + 16 * LDA_B);
#pragma unroll
            for (int mb = 0; mb < 2; ++mb) {
#pragma unroll
                for (int jn = 0; jn < 4; ++jn) {
                    MMA16816H(acc[mb][jn], &ah[mb * 4], bb[jn * 2], bb[jn * 2 + 1]);
                }
            }
        }

        int g = lane >> 2, t2 = (lane & 3) * 2;
#pragma unroll
        for (int mb = 0; mb < 2; ++mb) {
            int gr0 = row0 + wm * 32 + mb * 16 + g;
#pragma unroll
            for (int jn = 0; jn < 4; ++jn) {
                int gc = col0 + wn * 32 + jn * 8 + t2;
                float b0 = g_ball[gc], b1 = g_ball[gc + 1];
                float v00 = acc[mb][jn][0] + b0, v01 = acc[mb][jn][1] + b1;
                float v10 = acc[mb][jn][2] + b0, v11 = acc[mb][jn][3] + b1;
                if (sel == 0) {
                    if (gr0 < nrows)
                        *reinterpret_cast<__half2*>(&g_qh[(size_t)gr0 * QKVDIM + gc]) = __floats2half2_rn(v00, v01);
                    if (gr0 + 8 < nrows)
                        *reinterpret_cast<__half2*>(&g_qh[(size_t)(gr0 + 8) * QKVDIM + gc]) = __floats2half2_rn(v10, v11);
                } else if (sel == 3) {
                    int sc = gc - 768;
                    if (gr0 < nrows)
                        *reinterpret_cast<float2*>(g_skip + (size_t)gr0 * HID + sc) = make_float2(v00, v01);
                    if (gr0 + 8 < nrows)
                        *reinterpret_cast<float2*>(g_skip + (size_t)(gr0 + 8) * HID + sc) = make_float2(v10, v11);
                } else {
                    int koff = gc - 256;   // k: [0,256)  v: [256,512)
                    if (gr0 < nrows)
                        *reinterpret_cast<__half2*>(&g_kvh[(size_t)gr0 * 512 + koff]) = __floats2half2_rn(v00, v01);
                    if (gr0 + 8 < nrows)
                        *reinterpret_cast<__half2*>(&g_kvh[(size_t)(gr0 + 8) * 512 + koff]) = __floats2half2_rn(v10, v11);
                }
            }
        }
    }
}

// ---------------- fused attention + head mean + skip + tanh + MLP ----------------
// Grid-stride over groups of 8 nodes; Wms loaded once per block.
// Warp per node; predicated 4-edge batches; hsm is warp-private (syncwarp only).
__global__ void __launch_bounds__(256) attn_kernel(float* __restrict__ out, int n, int ngroups) {
    __shared__ float Wsm[64 * 66];
    __shared__ float hsm[8][64];
    int tid = threadIdx.x;
    int lane = tid & 31;
    int w = tid >> 5;

    for (int i = tid; i < 4096; i += 256) Wsm[(i >> 6) * 66 + (i & 63)] = g_Wms[i];
    __syncthreads();

    for (int grp = blockIdx.x; grp < ngroups; grp += gridDim.x) {
        int gw = grp * 8 + w;
        bool valid = gw < n;

        if (valid) {
            uint4 qv = *reinterpret_cast<const uint4*>(g_qh + (size_t)gw * QKVDIM + lane * 8);
            float2 q0 = __half22float2(*reinterpret_cast<__half2*>(&qv.x));
            float2 q1 = __half22float2(*reinterpret_cast<__half2*>(&qv.y));
            float2 q2 = __half22float2(*reinterpret_cast<__half2*>(&qv.z));
            float2 q3 = __half22float2(*reinterpret_cast<__half2*>(&qv.w));

            int start = g_rowstart[gw], end = g_rowstart[gw + 1];
            float S[8] = {0.f, 0.f, 0.f, 0.f, 0.f, 0.f, 0.f, 0.f};
            float d = 0.f;

            for (int p = start; p < end; p += 4) {
                int rem = end - p;  // >= 1
                int idx[4];
#pragma unroll
                for (int i = 0; i < 4; ++i) idx[i] = g_esrc[(i < rem) ? (p + i) : p];
                uint4 kk[4], vv[4];
#pragma unroll
                for (int i = 0; i < 4; ++i) {
                    const uint4* kv = reinterpret_cast<const uint4*>(g_kvh + (size_t)idx[i] * 512);
                    kk[i] = kv[lane];
                    vv[i] = kv[lane + 32];
                }
                float t[4];
#pragma unroll
                for (int i = 0; i < 4; ++i) {
                    float2 k0 = __half22float2(*reinterpret_cast<__half2*>(&kk[i].x));
                    float2 k1 = __half22float2(*reinterpret_cast<__half2*>(&kk[i].y));
                    float2 k2 = __half22float2(*reinterpret_cast<__half2*>(&kk[i].z));
                    float2 k3 = __half22float2(*reinterpret_cast<__half2*>(&kk[i].w));
                    t[i] = q0.x * k0.x + q0.y * k0.y + q1.x * k1.x + q1.y * k1.y
                         + q2.x * k2.x + q2.y * k2.y + q3.x * k3.x + q3.y * k3.y;
                }
#pragma unroll
                for (int i = 0; i < 4; ++i) t[i] += __shfl_xor_sync(0xFFFFFFFFu, t[i], 1);
#pragma unroll
                for (int i = 0; i < 4; ++i) t[i] += __shfl_xor_sync(0xFFFFFFFFu, t[i], 2);
#pragma unroll
                for (int i = 0; i < 4; ++i) t[i] += __shfl_xor_sync(0xFFFFFFFFu, t[i], 4);
                float e[4];
#pragma unroll
                for (int i = 0; i < 4; ++i) {
                    e[i] = (i < rem) ? __expf(t[i] * 0.125f) : 0.f;
                    d += e[i];
                }
#pragma unroll
                for (int i = 0; i < 4; ++i) {
                    float2 v0 = __half22float2(*reinterpret_cast<__half2*>(&vv[i].x));
                    float2 v1 = __half22float2(*reinterpret_cast<__half2*>(&vv[i].y));
                    float2 v2 = __half22float2(*reinterpret_cast<__half2*>(&vv[i].z));
                    float2 v3 = __half22float2(*reinterpret_cast<__half2*>(&vv[i].w));
                    S[0] += e[i] * v0.x; S[1] += e[i] * v0.y;
                    S[2] += e[i] * v1.x; S[3] += e[i] * v1.y;
                    S[4] += e[i] * v2.x; S[5] += e[i] * v2.y;
                    S[6] += e[i] * v3.x; S[7] += e[i] * v3.y;
                }
            }

            float r = 1.f / (d + 1e-16f);
#pragma unroll
            for (int j = 0; j < 8; ++j) {
                float s = S[j] * r;
                s += __shfl_xor_sync(0xFFFFFFFFu, s, 8);
                s += __shfl_xor_sync(0xFFFFFFFFu, s, 16);
                S[j] = s;
            }

            if (lane < 8) {
                const float* sk = g_skip + (size_t)gw * HID + lane * 8;
#pragma unroll
                for (int j = 0; j < 8; ++j)
                    hsm[w][lane * 8 + j] = tanhf(0.25f * S[j] + sk[j]);
            }
        }
        __syncwarp();

        if (valid) {
            const float* hrow = hsm[w];
            float acc0 = 0.f, acc1 = 0.f;
#pragma unroll 8
            for (int dd = 0; dd < 64; ++dd) {
                float hv = hrow[dd];
                float2 wv = *reinterpret_cast<const float2*>(&Wsm[dd * 66 + lane * 2]);
                acc0 += hv * wv.x;
                acc1 += hv * wv.y;
            }
            *reinterpret_cast<float2*>(out + (size_t)gw * OUTD + lane * 2) = make_float2(acc0, acc1);
        }
        __syncwarp();  // hsm[w] reads complete before next iteration overwrites
    }
}

// ---------------- launch ----------------
extern "C" void kernel_launch(void* const* d_in, const int* in_sizes, int n_in,
                              void* d_out, int out_size) {
    const float* x     = (const float*)d_in[0];
    const int*   ei    = (const int*)  d_in[1];
    const float* Wq    = (const float*)d_in[2];
    const float* bq    = (const float*)d_in[3];
    const float* Wk    = (const float*)d_in[4];
    const float* bk    = (const float*)d_in[5];
    const float* Wv    = (const float*)d_in[6];
    const float* bv    = (const float*)d_in[7];
    const float* Wskip = (const float*)d_in[8];
    const float* bskip = (const float*)d_in[9];
    const float* Wmlp  = (const float*)d_in[10];
    float* out = (float*)d_out;

    int N = in_sizes[0] / INDIM;
    int E = in_sizes[1] / 2;

    static cudaStream_t s2 = nullptr;
    static cudaEvent_t evFork = nullptr, evJoin = nullptr;
    if (s2 == nullptr) {
        cudaStreamCreateWithFlags(&s2, cudaStreamNonBlocking);
        cudaEventCreateWithFlags(&evFork, cudaEventDisableTiming);
        cudaEventCreateWithFlags(&evJoin, cudaEventDisableTiming);
    }
    cudaFuncSetAttribute(gemm_mma_kernel, cudaFuncAttributeMaxDynamicSharedMemorySize,
                         GEMM_SMEM_BYTES);

    // fork: CSR chain + sigma on s2; projections on default stream
    cudaEventRecord(evFork, 0);
    cudaStreamWaitEvent(s2, evFork, 0);

    zero_kernel<<<(N + 255) / 256, 256, 0, s2>>>(N);
    hist_kernel<<<(E + 255) / 256, 256, 0, s2>>>(ei, E);
    scan_kernel<<<1, 1024, 0, s2>>>(N);
    scatter_edges_kernel<<<(E + 255) / 256, 256, 0, s2>>>(ei, E);
    sigma_kernel<<<1, 32, 0, s2>>>(Wmlp);
    cudaEventRecord(evJoin, s2);

    prep_kernel<<<(COLS_ALL * INDIM + 255) / 256, 256>>>(Wq, bq, Wk, bk, Wv, bv, Wskip, bskip);
    int mblocks = (N + 127) / 128;
    dim3 ggrid(mblocks, 2);
    gemm_mma_kernel<<<ggrid, 256, GEMM_SMEM_BYTES>>>(x, N);

    // join, then fused attention + epilogue + MLP
    cudaStreamWaitEvent(0, evJoin, 0);
    int ngroups = (N + 7) / 8;
    int ablocks = ngroups < 1184 ? ngroups : 1184;
    attn_kernel<<<ablocks, 256>>>(out, N, ngroups);
}